// round 7
// baseline (speedup 1.0000x reference)
#include <cuda_runtime.h>
#include <math.h>

#define S_     2048
#define HID_   2048
#define H_     16
#define HKV_   4
#define D_     128
#define GROUPS_ 4
#define SCALE_ 0.08838834764831845f   // 128^-0.5
#define DECAY_CUT (-40.0f)

// ---------------- scratch (no cudaMalloc allowed) ----------------
__device__ float g_q   [S_*H_*D_];
__device__ float g_k   [S_*HKV_*D_];
__device__ float g_v   [S_*HKV_*D_];
__device__ float g_g   [S_*HKV_];
__device__ float g_gc  [HKV_*S_];
__device__ float g_attn[S_*H_*D_];
__device__ float g_hsr [S_*HID_];
__device__ float g_wqr [HID_*H_*D_];
__device__ float g_wkr [HID_*HKV_*D_];
__device__ float g_wvr [HID_*HKV_*D_];
__device__ float g_wor [H_*D_*HID_];

// ---------------- tf32 helpers ----------------
__device__ __forceinline__ unsigned f2tf(float x) {
    unsigned r; asm("cvt.rna.tf32.f32 %0, %1;" : "=r"(r) : "f"(x)); return r;
}
__device__ __forceinline__ void mma_tf32(float c[4], const unsigned a[4], const unsigned b[2]) {
    asm volatile("mma.sync.aligned.m16n8k8.row.col.f32.tf32.tf32.f32 "
        "{%0,%1,%2,%3},{%4,%5,%6,%7},{%8,%9},{%0,%1,%2,%3};"
        : "+f"(c[0]), "+f"(c[1]), "+f"(c[2]), "+f"(c[3])
        : "r"(a[0]), "r"(a[1]), "r"(a[2]), "r"(a[3]), "r"(b[0]), "r"(b[1]));
}
// split x into hi (tf32-truncated bits) + lo (exact residual)
__device__ __forceinline__ void split2(float x, unsigned& hi, unsigned& lo) {
    const unsigned h = __float_as_uint(x) & 0xffffe000u;
    hi = h;
    lo = __float_as_uint(x - __uint_as_float(h));
}
__device__ __forceinline__ void cpa16(void* sp, const void* gp) {
    unsigned s = (unsigned)__cvta_generic_to_shared(sp);
    asm volatile("cp.async.cg.shared.global [%0], [%1], 16;" :: "r"(s), "l"(gp));
}

// ---------------- pre-round f32 -> tf32(rna) bits ----------------
__global__ void preround(const float* __restrict__ s, float* __restrict__ d) {
    const size_t i = ((size_t)blockIdx.x * 256 + threadIdx.x) * 4;
    float4 v = *(const float4*)(s + i);
    v.x = __uint_as_float(f2tf(v.x));
    v.y = __uint_as_float(f2tf(v.y));
    v.z = __uint_as_float(f2tf(v.z));
    v.w = __uint_as_float(f2tf(v.w));
    *(float4*)(d + i) = v;
}

// ---------------- tf32 tensor-core GEMM: 256x128 tile, 512 threads --------
#define BM 256
#define BN 128
#define BK 32
#define PA 36
#define PB 136
#define NK 64
#define STG_A (BM*PA)
#define STG_B (BK*PB)
#define GEMM_SMEM3 (3*(STG_A+STG_B)*4)   // 162816 B

__device__ __forceinline__ void gemm_issue(const float* __restrict__ A,
        const float* __restrict__ B, int N, int bm, int bn,
        float* As, float* Bs, int kt,
        int arow, int acol, int brow, int bcol) {
    float* Ad = As + (kt % 3) * STG_A;
    const float* Ag = A + (size_t)bm * 2048 + kt * BK;
    #pragma unroll
    for (int i = 0; i < 4; i++) {
        const int r = arow + i * 64;
        cpa16(Ad + r * PA + acol, Ag + (size_t)r * 2048 + acol);
    }
    float* Bd = Bs + (kt % 3) * STG_B;
    const float* Bg = B + (size_t)(kt * BK) * N + bn;
    #pragma unroll
    for (int i = 0; i < 2; i++) {
        const int r = brow + i * 16;
        cpa16(Bd + r * PB + bcol, Bg + (size_t)r * N + bcol);
    }
    asm volatile("cp.async.commit_group;");
}

__device__ __forceinline__ void gemm_core(const float* __restrict__ A,
        const float* __restrict__ B, float* __restrict__ C,
        int N, int bm, int bn, float* As, float* Bs) {
    const int tid  = threadIdx.x;
    const int lane = tid & 31;
    const int warp = tid >> 5;
    const int wm   = (warp & 7) * 32;    // 8 warps along M
    const int wn   = (warp >> 3) * 64;   // 2 warps along N
    const int arow = tid >> 3, acol = (tid & 7) * 4;
    const int brow = tid >> 5, bcol = (tid & 31) * 4;

    float acc[2][8][4];
    #pragma unroll
    for (int mi = 0; mi < 2; mi++)
        #pragma unroll
        for (int ni = 0; ni < 8; ni++)
            #pragma unroll
            for (int r = 0; r < 4; r++) acc[mi][ni][r] = 0.f;

    gemm_issue(A, B, N, bm, bn, As, Bs, 0, arow, acol, brow, bcol);
    gemm_issue(A, B, N, bm, bn, As, Bs, 1, arow, acol, brow, bcol);

    for (int kt = 0; kt < NK; kt++) {
        asm volatile("cp.async.wait_group 1;");
        __syncthreads();

        const float* Ab = As + (kt % 3) * STG_A;
        const float* Bb = Bs + (kt % 3) * STG_B;
        #pragma unroll
        for (int ks = 0; ks < BK; ks += 8) {
            unsigned af[2][4], bf[8][2];
            #pragma unroll
            for (int mi = 0; mi < 2; mi++) {
                const int r = wm + mi * 16 + (lane >> 2);
                const int c = ks + (lane & 3);
                af[mi][0] = __float_as_uint(Ab[r * PA + c]);
                af[mi][1] = __float_as_uint(Ab[(r + 8) * PA + c]);
                af[mi][2] = __float_as_uint(Ab[r * PA + c + 4]);
                af[mi][3] = __float_as_uint(Ab[(r + 8) * PA + c + 4]);
            }
            #pragma unroll
            for (int ni = 0; ni < 8; ni++) {
                const int cn = wn + ni * 8 + (lane >> 2);
                const int rk = ks + (lane & 3);
                bf[ni][0] = __float_as_uint(Bb[rk * PB + cn]);
                bf[ni][1] = __float_as_uint(Bb[(rk + 4) * PB + cn]);
            }
            #pragma unroll
            for (int mi = 0; mi < 2; mi++)
                #pragma unroll
                for (int ni = 0; ni < 8; ni++)
                    mma_tf32(acc[mi][ni], af[mi], bf[ni]);
        }
        __syncthreads();

        if (kt + 2 < NK)
            gemm_issue(A, B, N, bm, bn, As, Bs, kt + 2, arow, acol, brow, bcol);
        else
            asm volatile("cp.async.commit_group;");
    }

    #pragma unroll
    for (int mi = 0; mi < 2; mi++) {
        const int r0 = bm + wm + mi * 16 + (lane >> 2);
        #pragma unroll
        for (int ni = 0; ni < 8; ni++) {
            const int c0 = bn + wn + ni * 8 + 2 * (lane & 3);
            *(float2*)(C + (size_t)r0 * N + c0)       = make_float2(acc[mi][ni][0], acc[mi][ni][1]);
            *(float2*)(C + (size_t)(r0 + 8) * N + c0) = make_float2(acc[mi][ni][2], acc[mi][ni][3]);
        }
    }
}

__global__ void __launch_bounds__(512, 1) gemm_qkv(const float* __restrict__ A,
        const float* __restrict__ Bq, const float* __restrict__ Bk,
        const float* __restrict__ Bv) {
    extern __shared__ float smf[];
    const int bx = blockIdx.x;
    const float* Bm; float* Cm; int N, bn;
    if (bx < 16)      { Bm = Bq; Cm = g_q; N = 2048; bn = bx * 128; }
    else if (bx < 20) { Bm = Bk; Cm = g_k; N = 512;  bn = (bx - 16) * 128; }
    else              { Bm = Bv; Cm = g_v; N = 512;  bn = (bx - 20) * 128; }
    gemm_core(A, Bm, Cm, N, blockIdx.y * BM, bn, smf, smf + 3 * STG_A);
}

__global__ void __launch_bounds__(512, 1) gemm_wo(const float* __restrict__ A,
        const float* __restrict__ B, float* __restrict__ C) {
    extern __shared__ float smf[];
    gemm_core(A, B, C, HID_, blockIdx.y * BM, blockIdx.x * BN, smf, smf + 3 * STG_A);
}

// ---------------- gate projection (exact fp32) ----------------
__global__ void gate_proj(const float* __restrict__ hs, const float* __restrict__ Wg) {
    const int s = blockIdx.x;
    const int w = threadIdx.x >> 5, l = threadIdx.x & 31;
    const float* row = hs + (size_t)s * HID_;
    float acc = 0.f;
    for (int k = l; k < HID_; k += 32)
        acc = fmaf(row[k], Wg[k * HKV_ + w], acc);
    #pragma unroll
    for (int o = 16; o > 0; o >>= 1)
        acc += __shfl_down_sync(0xffffffffu, acc, o);
    if (l == 0) g_g[s * HKV_ + w] = acc;
}

// ---------------- log-sigmoid + parallel cumsum ----------------
__global__ void gcumsum_kernel() {
    __shared__ float ps[256];
    const int kv = blockIdx.x;
    const int t = threadIdx.x;
    float loc[8]; float s = 0.f;
    #pragma unroll
    for (int i = 0; i < 8; i++) {
        const float x = g_g[(t * 8 + i) * HKV_ + kv];
        const float ls = (x > 0.f) ? -log1pf(__expf(-x)) : x - log1pf(__expf(x));
        loc[i] = ls; s += ls;
    }
    ps[t] = s; __syncthreads();
    for (int o = 1; o < 256; o <<= 1) {
        const float v = (t >= o) ? ps[t - o] : 0.f;
        __syncthreads();
        ps[t] += v;
        __syncthreads();
    }
    float run = (t > 0) ? ps[t - 1] : 0.f;
    #pragma unroll
    for (int i = 0; i < 8; i++) {
        run += loc[i];
        g_gc[kv * S_ + t * 8 + i] = run;
    }
}

// ---------------- RoPE (in place) ----------------
__global__ void rope_kernel(float* __restrict__ x, const float* __restrict__ cosb,
                            const float* __restrict__ sinb, int nheads) {
    const int idx = blockIdx.x * blockDim.x + threadIdx.x;
    const int total = S_ * nheads * 64;
    if (idx >= total) return;
    const int d = idx % 64;
    const int h = (idx / 64) % nheads;
    const int s = idx / (64 * nheads);
    const float c  = cosb[s * 128 + d];
    const float sn = sinb[s * 128 + d];
    float* row = x + (size_t)s * nheads * 128 + h * 128;
    const float x0 = row[d], x1 = row[d + 64];
    row[d]      = x0 * c - x1 * sn;
    row[d + 64] = x1 * c + x0 * sn;
}

// ---------------- tensor-core causal power attention (3xTF32) ----------------
// K and V(transposed) share one smem buffer -> 86.8KB -> 2 CTAs/SM.
#define PQK 132   // Q/K pitch (%32==4, row-indexed frags conflict-free)
#define PVT 68    // transposed-V pitch [128][68] (%32==4, col frags conflict-free)
#define PS  68
#define ATTN_SMEM ((64*PQK + 128*PVT + 64*PS + 192) * 4)   // 86784 B

__global__ void __launch_bounds__(256, 2) attn_kernel() {
    extern __shared__ float sm[];
    float* Qs  = sm;                    // [64][PQK]
    float* KV  = Qs + 64 * PQK;         // K:[64][PQK] then VsT:[128][PVT]
    float* Ss  = KV + 128 * PVT;        // [64][PS]
    float* Gq  = Ss + 64 * PS;
    float* Gk  = Gq + 64;
    float* den = Gk + 64;

    const int qb = gridDim.x - 1 - blockIdx.x;   // big tiles first
    const int h = blockIdx.y, kv = h / GROUPS_;
    const int tid  = threadIdx.x;
    const int lane = tid & 31, warp = tid >> 5;
    const int ly = lane >> 2, lx = lane & 3;
    const int wm  = (warp & 3) * 16;     // row range
    const int wn  = (warp >> 2) * 32;    // QK col range
    const int wn2 = (warp >> 2) * 64;    // SV dim range

    #pragma unroll
    for (int j = 0; j < 8; j++) {
        const int idx = j * 256 + tid;
        const int r = idx >> 5, d = (idx & 31) * 4;
        *(float4*)(Qs + r * PQK + d) =
            *(const float4*)(g_q + (size_t)(qb * 64 + r) * (H_ * D_) + h * D_ + d);
    }
    if (tid < 64) { Gq[tid] = g_gc[kv * S_ + qb * 64 + tid]; den[tid] = 0.f; }
    __syncthreads();

    const float gq0 = Gq[wm + ly];
    const float gq1 = Gq[wm + ly + 8];
    const float Gq0 = Gq[0];

    float o[8][4];
    #pragma unroll
    for (int ni = 0; ni < 8; ni++)
        #pragma unroll
        for (int r = 0; r < 4; r++) o[ni][r] = 0.f;
    float rs0 = 0.f, rs1 = 0.f;

    for (int kb = qb; kb >= 0; kb--) {
        if (kb < qb && Gq0 - g_gc[kv * S_ + kb * 64 + 63] < DECAY_CUT) break;
        __syncthreads();   // prev SV done reading VsT/Ss
        // ---- load K tile (row-major, pitch PQK) ----
        #pragma unroll
        for (int j = 0; j < 8; j++) {
            const int idx = j * 256 + tid;
            const int r = idx >> 5, d = (idx & 31) * 4;
            *(float4*)(KV + r * PQK + d) =
                *(const float4*)(g_k + (size_t)(kb * 64 + r) * (HKV_ * D_) + kv * D_ + d);
        }
        if (tid < 64) Gk[tid] = g_gc[kv * S_ + kb * 64 + tid];
        __syncthreads();

        // ---- S = QK^T (3xTF32 mma) ----
        float c[4][4];
        #pragma unroll
        for (int ni = 0; ni < 4; ni++)
            #pragma unroll
            for (int r = 0; r < 4; r++) c[ni][r] = 0.f;
        #pragma unroll
        for (int ks = 0; ks < 128; ks += 8) {
            unsigned ah[4], al[4];
            const float* Qr = Qs + (wm + ly) * PQK + ks + lx;
            split2(Qr[0],           ah[0], al[0]);
            split2(Qr[8 * PQK],     ah[1], al[1]);
            split2(Qr[4],           ah[2], al[2]);
            split2(Qr[8 * PQK + 4], ah[3], al[3]);
            #pragma unroll
            for (int ni = 0; ni < 4; ni++) {
                unsigned bh[2], bl[2];
                const float* Kr = KV + (wn + ni * 8 + ly) * PQK + ks + lx;
                split2(Kr[0], bh[0], bl[0]);
                split2(Kr[4], bh[1], bl[1]);
                mma_tf32(c[ni], ah, bh);
                mma_tf32(c[ni], al, bh);
                mma_tf32(c[ni], ah, bl);
            }
        }

        // ---- mask, scale^2, decay; rowsums; stage S to smem ----
        const int rg0 = qb * 64 + wm + ly;
        const int rg1 = rg0 + 8;
        #pragma unroll
        for (int ni = 0; ni < 4; ni++) {
            const int col = wn + ni * 8 + 2 * lx;
            const int cg  = kb * 64 + col;
            const float gk0 = Gk[col], gk1 = Gk[col + 1];
            float t;
            t = c[ni][0] * SCALE_;
            const float v00 = (cg     <= rg0) ? t * t * __expf(gq0 - gk0) : 0.f;
            t = c[ni][1] * SCALE_;
            const float v01 = (cg + 1 <= rg0) ? t * t * __expf(gq0 - gk1) : 0.f;
            t = c[ni][2] * SCALE_;
            const float v10 = (cg     <= rg1) ? t * t * __expf(gq1 - gk0) : 0.f;
            t = c[ni][3] * SCALE_;
            const float v11 = (cg + 1 <= rg1) ? t * t * __expf(gq1 - gk1) : 0.f;
            rs0 += v00 + v01;
            rs1 += v10 + v11;
            *(float2*)(Ss + (wm + ly) * PS + col)     = make_float2(v00, v01);
            *(float2*)(Ss + (wm + ly + 8) * PS + col) = make_float2(v10, v11);
        }
        __syncthreads();   // QK done reading K; S visible

        // ---- load V transposed into the K buffer: VsT[d][j] ----
        #pragma unroll
        for (int j = 0; j < 8; j++) {
            const int idx = j * 256 + tid;
            const int r = idx >> 5, d0 = (idx & 31) * 4;
            const float4 v =
                *(const float4*)(g_v + (size_t)(kb * 64 + r) * (HKV_ * D_) + kv * D_ + d0);
            KV[(d0 + 0) * PVT + r] = v.x;
            KV[(d0 + 1) * PVT + r] = v.y;
            KV[(d0 + 2) * PVT + r] = v.z;
            KV[(d0 + 3) * PVT + r] = v.w;
        }
        __syncthreads();

        // ---- O += S @ V (3xTF32 mma) ----
        #pragma unroll
        for (int ks = 0; ks < 64; ks += 8) {
            unsigned ah[4], al[4];
            const float* Sr = Ss + (wm + ly) * PS + ks + lx;
            split2(Sr[0],          ah[0], al[0]);
            split2(Sr[8 * PS],     ah[1], al[1]);
            split2(Sr[4],          ah[2], al[2]);
            split2(Sr[8 * PS + 4], ah[3], al[3]);
            #pragma unroll
            for (int ni = 0; ni < 8; ni++) {
                unsigned bh[2], bl[2];
                const float* Vr = KV + (wn2 + ni * 8 + ly) * PVT + ks + lx;
                split2(Vr[0], bh[0], bl[0]);
                split2(Vr[4], bh[1], bl[1]);
                mma_tf32(o[ni], ah, bh);
                mma_tf32(o[ni], al, bh);
                mma_tf32(o[ni], ah, bl);
            }
        }
    }

    rs0 += __shfl_xor_sync(0xffffffffu, rs0, 1);
    rs0 += __shfl_xor_sync(0xffffffffu, rs0, 2);
    rs1 += __shfl_xor_sync(0xffffffffu, rs1, 1);
    rs1 += __shfl_xor_sync(0xffffffffu, rs1, 2);
    if (lx == 0) {
        atomicAdd(&den[wm + ly], rs0);
        atomicAdd(&den[wm + ly + 8], rs1);
    }
    __syncthreads();

    const float inv0 = 1.f / fmaxf(den[wm + ly], 1.f);
    const float inv1 = 1.f / fmaxf(den[wm + ly + 8], 1.f);
    #pragma unroll
    for (int ni = 0; ni < 8; ni++) {
        const int colg = h * D_ + wn2 + ni * 8 + 2 * lx;
        float* d0 = g_attn + (size_t)(qb * 64 + wm + ly) * (H_ * D_) + colg;
        float* d1 = g_attn + (size_t)(qb * 64 + wm + ly + 8) * (H_ * D_) + colg;
        *(float2*)d0 = make_float2(o[ni][0] * inv0, o[ni][1] * inv0);
        *(float2*)d1 = make_float2(o[ni][2] * inv1, o[ni][3] * inv1);
    }
}

// ---------------- launch ----------------
extern "C" void kernel_launch(void* const* d_in, const int* in_sizes, int n_in,
                              void* d_out, int out_size) {
    (void)in_sizes; (void)n_in; (void)out_size;
    const float* hs   = (const float*)d_in[0];
    const float* cosb = (const float*)d_in[1];
    const float* sinb = (const float*)d_in[2];
    const float* Wq   = (const float*)d_in[3];
    const float* Wk   = (const float*)d_in[4];
    const float* Wv   = (const float*)d_in[5];
    const float* Wg   = (const float*)d_in[6];
    const float* Wo   = (const float*)d_in[7];
    float* out = (float*)d_out;

    float *q, *k, *attn, *hsr, *wqr, *wkr, *wvr, *wor;
    cudaGetSymbolAddress((void**)&q,    g_q);
    cudaGetSymbolAddress((void**)&k,    g_k);
    cudaGetSymbolAddress((void**)&attn, g_attn);
    cudaGetSymbolAddress((void**)&hsr,  g_hsr);
    cudaGetSymbolAddress((void**)&wqr,  g_wqr);
    cudaGetSymbolAddress((void**)&wkr,  g_wkr);
    cudaGetSymbolAddress((void**)&wvr,  g_wvr);
    cudaGetSymbolAddress((void**)&wor,  g_wor);

    static cudaStream_t s1 = nullptr, s2 = nullptr, s3 = nullptr;
    static cudaEvent_t ev0, ev1, ev2, ev2a, ev3;
    if (!s1) {
        cudaStreamCreateWithFlags(&s1, cudaStreamNonBlocking);
        cudaStreamCreateWithFlags(&s2, cudaStreamNonBlocking);
        cudaStreamCreateWithFlags(&s3, cudaStreamNonBlocking);
        cudaEventCreateWithFlags(&ev0,  cudaEventDisableTiming);
        cudaEventCreateWithFlags(&ev1,  cudaEventDisableTiming);
        cudaEventCreateWithFlags(&ev2,  cudaEventDisableTiming);
        cudaEventCreateWithFlags(&ev2a, cudaEventDisableTiming);
        cudaEventCreateWithFlags(&ev3,  cudaEventDisableTiming);
    }

    cudaFuncSetAttribute(gemm_qkv, cudaFuncAttributeMaxDynamicSharedMemorySize, GEMM_SMEM3);
    cudaFuncSetAttribute(gemm_wo,  cudaFuncAttributeMaxDynamicSharedMemorySize, GEMM_SMEM3);
    cudaFuncSetAttribute(attn_kernel, cudaFuncAttributeMaxDynamicSharedMemorySize, ATTN_SMEM);

    cudaEventRecord(ev0, 0);

    // side stream 2: Wq preround
    cudaStreamWaitEvent(s2, ev0, 0);
    preround<<<(HID_*H_*D_)   / 1024, 256, 0, s2>>>(Wq, wqr);
    cudaEventRecord(ev2a, s2);

    // side stream 3: Wk, Wv, then Wo prerounds
    cudaStreamWaitEvent(s3, ev0, 0);
    preround<<<(HID_*HKV_*D_) / 1024, 256, 0, s3>>>(Wk, wkr);
    preround<<<(HID_*HKV_*D_) / 1024, 256, 0, s3>>>(Wv, wvr);
    cudaEventRecord(ev3, s3);
    preround<<<(H_*D_*HID_)   / 1024, 256, 0, s3>>>(Wo, wor);
    cudaEventRecord(ev2, s3);

    // side stream 1: gate path (exact fp32)
    cudaStreamWaitEvent(s1, ev0, 0);
    gate_proj<<<S_, 128, 0, s1>>>(hs, Wg);
    gcumsum_kernel<<<HKV_, 256, 0, s1>>>();
    cudaEventRecord(ev1, s1);

    // main stream
    preround<<<(S_*HID_) / 1024, 256>>>(hs, hsr);
    cudaStreamWaitEvent(0, ev2a, 0);
    cudaStreamWaitEvent(0, ev3, 0);
    gemm_qkv<<<dim3(24, S_ / BM), 512, GEMM_SMEM3>>>(hsr, wqr, wkr, wvr);
    rope_kernel<<<(S_*H_*64   + 255) / 256, 256>>>(q, cosb, sinb, H_);
    rope_kernel<<<(S_*HKV_*64 + 255) / 256, 256>>>(k, cosb, sinb, HKV_);

    cudaStreamWaitEvent(0, ev1, 0);
    attn_kernel<<<dim3(S_ / 64, H_), 256, ATTN_SMEM>>>();

    cudaStreamWaitEvent(0, ev2, 0);
    gemm_wo<<<dim3(HID_ / BN, S_ / BM), 512, GEMM_SMEM3>>>(attn, wor, out);
}

// round 8
// speedup vs baseline: 1.1964x; 1.1964x over previous
#include <cuda_runtime.h>
#include <math.h>

#define S_     2048
#define HID_   2048
#define H_     16
#define HKV_   4
#define D_     128
#define GROUPS_ 4
#define SCALE_ 0.08838834764831845f   // 128^-0.5
#define DECAY_CUT (-40.0f)

// ---------------- scratch (no cudaMalloc allowed) ----------------
__device__ float g_q   [S_*H_*D_];
__device__ float g_k   [S_*HKV_*D_];
__device__ float g_v   [S_*HKV_*D_];
__device__ float g_g   [S_*HKV_];
__device__ float g_gc  [HKV_*S_];
__device__ float g_attn[S_*H_*D_];
__device__ float g_hsr [S_*HID_];
__device__ float g_wqr [HID_*H_*D_];
__device__ float g_wkr [HID_*HKV_*D_];
__device__ float g_wvr [HID_*HKV_*D_];
__device__ float g_wor [H_*D_*HID_];

// ---------------- tf32 helpers ----------------
__device__ __forceinline__ unsigned f2tf(float x) {
    unsigned r; asm("cvt.rna.tf32.f32 %0, %1;" : "=r"(r) : "f"(x)); return r;
}
__device__ __forceinline__ void mma_tf32(float c[4], const unsigned a[4], const unsigned b[2]) {
    asm volatile("mma.sync.aligned.m16n8k8.row.col.f32.tf32.tf32.f32 "
        "{%0,%1,%2,%3},{%4,%5,%6,%7},{%8,%9},{%0,%1,%2,%3};"
        : "+f"(c[0]), "+f"(c[1]), "+f"(c[2]), "+f"(c[3])
        : "r"(a[0]), "r"(a[1]), "r"(a[2]), "r"(a[3]), "r"(b[0]), "r"(b[1]));
}
// split x into hi (tf32-truncated bits) + lo (exact residual)
__device__ __forceinline__ void split2(float x, unsigned& hi, unsigned& lo) {
    const unsigned h = __float_as_uint(x) & 0xffffe000u;
    hi = h;
    lo = __float_as_uint(x - __uint_as_float(h));
}
__device__ __forceinline__ void cpa16(void* sp, const void* gp) {
    unsigned s = (unsigned)__cvta_generic_to_shared(sp);
    asm volatile("cp.async.cg.shared.global [%0], [%1], 16;" :: "r"(s), "l"(gp));
}

// ---------------- pre-round f32 -> tf32(rna) bits ----------------
__global__ void preround(const float* __restrict__ s, float* __restrict__ d) {
    const size_t i = ((size_t)blockIdx.x * 256 + threadIdx.x) * 4;
    float4 v = *(const float4*)(s + i);
    v.x = __uint_as_float(f2tf(v.x));
    v.y = __uint_as_float(f2tf(v.y));
    v.z = __uint_as_float(f2tf(v.z));
    v.w = __uint_as_float(f2tf(v.w));
    *(float4*)(d + i) = v;
}

// ---------------- tf32 tensor-core GEMM (R6 config: 128x128, occ 2) ------
#define BM 128
#define BN 128
#define BK 32
#define PA 36
#define PB 136
#define NK 64
#define STG_A (BM*PA)
#define STG_B (BK*PB)
#define GEMM_SMEM3 (3*(STG_A+STG_B)*4)   // 107520 B

__device__ __forceinline__ void gemm_issue(const float* __restrict__ A,
        const float* __restrict__ B, int N, int bm, int bn,
        float* As, float* Bs, int kt,
        int arow, int acol, int brow, int bcol) {
    float* Ad = As + (kt % 3) * STG_A;
    const float* Ag = A + (size_t)bm * 2048 + kt * BK;
    #pragma unroll
    for (int i = 0; i < 4; i++) {
        const int r = arow + i * 32;
        cpa16(Ad + r * PA + acol, Ag + (size_t)r * 2048 + acol);
    }
    float* Bd = Bs + (kt % 3) * STG_B;
    const float* Bg = B + (size_t)(kt * BK) * N + bn;
    #pragma unroll
    for (int i = 0; i < 4; i++) {
        const int r = brow + i * 8;
        cpa16(Bd + r * PB + bcol, Bg + (size_t)r * N + bcol);
    }
    asm volatile("cp.async.commit_group;");
}

__device__ __forceinline__ void gemm_core(const float* __restrict__ A,
        const float* __restrict__ B, float* __restrict__ C,
        int N, int bm, int bn, float* As, float* Bs) {
    const int tid  = threadIdx.x;
    const int lane = tid & 31;
    const int warp = tid >> 5;
    const int wm   = (warp & 3) * 32;
    const int wn   = (warp >> 2) * 64;
    const int arow = tid >> 3, acol = (tid & 7) * 4;
    const int brow = tid >> 5, bcol = (tid & 31) * 4;

    float acc[2][8][4];
    #pragma unroll
    for (int mi = 0; mi < 2; mi++)
        #pragma unroll
        for (int ni = 0; ni < 8; ni++)
            #pragma unroll
            for (int r = 0; r < 4; r++) acc[mi][ni][r] = 0.f;

    gemm_issue(A, B, N, bm, bn, As, Bs, 0, arow, acol, brow, bcol);
    gemm_issue(A, B, N, bm, bn, As, Bs, 1, arow, acol, brow, bcol);

    for (int kt = 0; kt < NK; kt++) {
        asm volatile("cp.async.wait_group 1;");
        __syncthreads();

        const float* Ab = As + (kt % 3) * STG_A;
        const float* Bb = Bs + (kt % 3) * STG_B;
        #pragma unroll
        for (int ks = 0; ks < BK; ks += 8) {
            unsigned af[2][4], bf[8][2];
            #pragma unroll
            for (int mi = 0; mi < 2; mi++) {
                const int r = wm + mi * 16 + (lane >> 2);
                const int c = ks + (lane & 3);
                af[mi][0] = __float_as_uint(Ab[r * PA + c]);
                af[mi][1] = __float_as_uint(Ab[(r + 8) * PA + c]);
                af[mi][2] = __float_as_uint(Ab[r * PA + c + 4]);
                af[mi][3] = __float_as_uint(Ab[(r + 8) * PA + c + 4]);
            }
            #pragma unroll
            for (int ni = 0; ni < 8; ni++) {
                const int cn = wn + ni * 8 + (lane >> 2);
                const int rk = ks + (lane & 3);
                bf[ni][0] = __float_as_uint(Bb[rk * PB + cn]);
                bf[ni][1] = __float_as_uint(Bb[(rk + 4) * PB + cn]);
            }
            #pragma unroll
            for (int mi = 0; mi < 2; mi++)
                #pragma unroll
                for (int ni = 0; ni < 8; ni++)
                    mma_tf32(acc[mi][ni], af[mi], bf[ni]);
        }
        __syncthreads();

        if (kt + 2 < NK)
            gemm_issue(A, B, N, bm, bn, As, Bs, kt + 2, arow, acol, brow, bcol);
        else
            asm volatile("cp.async.commit_group;");
    }

    #pragma unroll
    for (int mi = 0; mi < 2; mi++) {
        const int r0 = bm + wm + mi * 16 + (lane >> 2);
        #pragma unroll
        for (int ni = 0; ni < 8; ni++) {
            const int c0 = bn + wn + ni * 8 + 2 * (lane & 3);
            *(float2*)(C + (size_t)r0 * N + c0)       = make_float2(acc[mi][ni][0], acc[mi][ni][1]);
            *(float2*)(C + (size_t)(r0 + 8) * N + c0) = make_float2(acc[mi][ni][2], acc[mi][ni][3]);
        }
    }
}

__global__ void __launch_bounds__(256, 2) gemm_qkv(const float* __restrict__ A,
        const float* __restrict__ Bq, const float* __restrict__ Bk,
        const float* __restrict__ Bv) {
    extern __shared__ float smf[];
    const int bx = blockIdx.x;
    const float* Bm; float* Cm; int N, bn;
    if (bx < 16)      { Bm = Bq; Cm = g_q; N = 2048; bn = bx * 128; }
    else if (bx < 20) { Bm = Bk; Cm = g_k; N = 512;  bn = (bx - 16) * 128; }
    else              { Bm = Bv; Cm = g_v; N = 512;  bn = (bx - 20) * 128; }
    gemm_core(A, Bm, Cm, N, blockIdx.y * BM, bn, smf, smf + 3 * STG_A);
}

__global__ void __launch_bounds__(256, 2) gemm_wo(const float* __restrict__ A,
        const float* __restrict__ B, float* __restrict__ C) {
    extern __shared__ float smf[];
    gemm_core(A, B, C, HID_, blockIdx.y * BM, blockIdx.x * BN, smf, smf + 3 * STG_A);
}

// ---------------- gate projection (exact fp32) ----------------
__global__ void gate_proj(const float* __restrict__ hs, const float* __restrict__ Wg) {
    const int s = blockIdx.x;
    const int w = threadIdx.x >> 5, l = threadIdx.x & 31;
    const float* row = hs + (size_t)s * HID_;
    float acc = 0.f;
    for (int k = l; k < HID_; k += 32)
        acc = fmaf(row[k], Wg[k * HKV_ + w], acc);
    #pragma unroll
    for (int o = 16; o > 0; o >>= 1)
        acc += __shfl_down_sync(0xffffffffu, acc, o);
    if (l == 0) g_g[s * HKV_ + w] = acc;
}

// ---------------- log-sigmoid + parallel cumsum ----------------
__global__ void gcumsum_kernel() {
    __shared__ float ps[256];
    const int kv = blockIdx.x;
    const int t = threadIdx.x;
    float loc[8]; float s = 0.f;
    #pragma unroll
    for (int i = 0; i < 8; i++) {
        const float x = g_g[(t * 8 + i) * HKV_ + kv];
        const float ls = (x > 0.f) ? -log1pf(__expf(-x)) : x - log1pf(__expf(x));
        loc[i] = ls; s += ls;
    }
    ps[t] = s; __syncthreads();
    for (int o = 1; o < 256; o <<= 1) {
        const float v = (t >= o) ? ps[t - o] : 0.f;
        __syncthreads();
        ps[t] += v;
        __syncthreads();
    }
    float run = (t > 0) ? ps[t - 1] : 0.f;
    #pragma unroll
    for (int i = 0; i < 8; i++) {
        run += loc[i];
        g_gc[kv * S_ + t * 8 + i] = run;
    }
}

// ---------------- RoPE (in place) ----------------
__global__ void rope_kernel(float* __restrict__ x, const float* __restrict__ cosb,
                            const float* __restrict__ sinb, int nheads) {
    const int idx = blockIdx.x * blockDim.x + threadIdx.x;
    const int total = S_ * nheads * 64;
    if (idx >= total) return;
    const int d = idx % 64;
    const int h = (idx / 64) % nheads;
    const int s = idx / (64 * nheads);
    const float c  = cosb[s * 128 + d];
    const float sn = sinb[s * 128 + d];
    float* row = x + (size_t)s * nheads * 128 + h * 128;
    const float x0 = row[d], x1 = row[d + 64];
    row[d]      = x0 * c - x1 * sn;
    row[d + 64] = x1 * c + x0 * sn;
}

// ---------------- tensor-core causal power attention (3xTF32) ----------------
// R6 layout, but Ss ALIASES the Ks buffer (S is written only after all K
// fragment reads finish; one extra barrier enforces it). 103168 B -> 2 CTAs/SM.
#define PQK 132   // Q/K pitch (%32==4, row-indexed frags conflict-free)
#define PV  136   // V pitch (%32==8, col-indexed frags conflict-free)
#define PS  68    // S pitch inside the K buffer (%32==4)
#define ATTN_SMEM ((2*64*PQK + 64*PV + 192) * 4)   // 103168 B

__global__ void __launch_bounds__(256, 2) attn_kernel() {
    extern __shared__ float sm[];
    float* Qs  = sm;                    // [64][PQK]
    float* Ks  = Qs + 64 * PQK;         // [64][PQK]; S tile reuses this region
    float* Ss  = Ks;                    // [64][PS]  (alias)
    float* Vs  = Ks + 64 * PQK;         // [64][PV]
    float* Gq  = Vs + 64 * PV;
    float* Gk  = Gq + 64;
    float* den = Gk + 64;

    const int qb = gridDim.x - 1 - blockIdx.x;   // big tiles first
    const int h = blockIdx.y, kv = h / GROUPS_;
    const int tid  = threadIdx.x;
    const int lane = tid & 31, warp = tid >> 5;
    const int ly = lane >> 2, lx = lane & 3;
    const int wm  = (warp & 3) * 16;     // row range
    const int wn  = (warp >> 2) * 32;    // QK col range
    const int wn2 = (warp >> 2) * 64;    // SV dim range

    #pragma unroll
    for (int j = 0; j < 8; j++) {
        const int idx = j * 256 + tid;
        const int r = idx >> 5, d = (idx & 31) * 4;
        *(float4*)(Qs + r * PQK + d) =
            *(const float4*)(g_q + (size_t)(qb * 64 + r) * (H_ * D_) + h * D_ + d);
    }
    if (tid < 64) { Gq[tid] = g_gc[kv * S_ + qb * 64 + tid]; den[tid] = 0.f; }
    __syncthreads();

    const float gq0 = Gq[wm + ly];
    const float gq1 = Gq[wm + ly + 8];
    const float Gq0 = Gq[0];

    float o[8][4];
    #pragma unroll
    for (int ni = 0; ni < 8; ni++)
        #pragma unroll
        for (int r = 0; r < 4; r++) o[ni][r] = 0.f;
    float rs0 = 0.f, rs1 = 0.f;

    for (int kb = qb; kb >= 0; kb--) {
        if (kb < qb && Gq0 - g_gc[kv * S_ + kb * 64 + 63] < DECAY_CUT) break;
        __syncthreads();   // prev SV done reading Ss/Vs
        #pragma unroll
        for (int j = 0; j < 8; j++) {
            const int idx = j * 256 + tid;
            const int r = idx >> 5, d = (idx & 31) * 4;
            const size_t gbase = (size_t)(kb * 64 + r) * (HKV_ * D_) + kv * D_ + d;
            *(float4*)(Ks + r * PQK + d) = *(const float4*)(g_k + gbase);
            *(float4*)(Vs + r * PV  + d) = *(const float4*)(g_v + gbase);
        }
        if (tid < 64) Gk[tid] = g_gc[kv * S_ + kb * 64 + tid];
        __syncthreads();

        // ---- S = QK^T (3xTF32 mma) ----
        float c[4][4];
        #pragma unroll
        for (int ni = 0; ni < 4; ni++)
            #pragma unroll
            for (int r = 0; r < 4; r++) c[ni][r] = 0.f;
        #pragma unroll
        for (int ks = 0; ks < 128; ks += 8) {
            unsigned ah[4], al[4];
            const float* Qr = Qs + (wm + ly) * PQK + ks + lx;
            split2(Qr[0],           ah[0], al[0]);
            split2(Qr[8 * PQK],     ah[1], al[1]);
            split2(Qr[4],           ah[2], al[2]);
            split2(Qr[8 * PQK + 4], ah[3], al[3]);
            #pragma unroll
            for (int ni = 0; ni < 4; ni++) {
                unsigned bh[2], bl[2];
                const float* Kr = Ks + (wn + ni * 8 + ly) * PQK + ks + lx;
                split2(Kr[0], bh[0], bl[0]);
                split2(Kr[4], bh[1], bl[1]);
                mma_tf32(c[ni], ah, bh);
                mma_tf32(c[ni], al, bh);
                mma_tf32(c[ni], ah, bl);
            }
        }
        // gather gate values BEFORE the barrier that allows S to overwrite K
        float gk0v[4], gk1v[4];
        #pragma unroll
        for (int ni = 0; ni < 4; ni++) {
            const int col = wn + ni * 8 + 2 * lx;
            gk0v[ni] = Gk[col];
            gk1v[ni] = Gk[col + 1];
        }
        __syncthreads();   // ALL warps done reading Ks -> safe to overwrite with S

        // ---- mask, scale^2, decay; rowsums; stage S into the K buffer ----
        const int rg0 = qb * 64 + wm + ly;
        const int rg1 = rg0 + 8;
        #pragma unroll
        for (int ni = 0; ni < 4; ni++) {
            const int col = wn + ni * 8 + 2 * lx;
            const int cg  = kb * 64 + col;
            float t;
            t = c[ni][0] * SCALE_;
            const float v00 = (cg     <= rg0) ? t * t * __expf(gq0 - gk0v[ni]) : 0.f;
            t = c[ni][1] * SCALE_;
            const float v01 = (cg + 1 <= rg0) ? t * t * __expf(gq0 - gk1v[ni]) : 0.f;
            t = c[ni][2] * SCALE_;
            const float v10 = (cg     <= rg1) ? t * t * __expf(gq1 - gk0v[ni]) : 0.f;
            t = c[ni][3] * SCALE_;
            const float v11 = (cg + 1 <= rg1) ? t * t * __expf(gq1 - gk1v[ni]) : 0.f;
            rs0 += v00 + v01;
            rs1 += v10 + v11;
            *(float2*)(Ss + (wm + ly) * PS + col)     = make_float2(v00, v01);
            *(float2*)(Ss + (wm + ly + 8) * PS + col) = make_float2(v10, v11);
        }
        __syncthreads();   // S visible to all warps

        // ---- O += S @ V (3xTF32 mma) ----
        #pragma unroll
        for (int ks = 0; ks < 64; ks += 8) {
            unsigned ah[4], al[4];
            const float* Sr = Ss + (wm + ly) * PS + ks + lx;
            split2(Sr[0],          ah[0], al[0]);
            split2(Sr[8 * PS],     ah[1], al[1]);
            split2(Sr[4],          ah[2], al[2]);
            split2(Sr[8 * PS + 4], ah[3], al[3]);
            #pragma unroll
            for (int ni = 0; ni < 8; ni++) {
                unsigned bh[2], bl[2];
                const float* Vr = Vs + (ks + lx) * PV + wn2 + ni * 8 + ly;
                split2(Vr[0],      bh[0], bl[0]);
                split2(Vr[4 * PV], bh[1], bl[1]);
                mma_tf32(o[ni], ah, bh);
                mma_tf32(o[ni], al, bh);
                mma_tf32(o[ni], ah, bl);
            }
        }
    }

    rs0 += __shfl_xor_sync(0xffffffffu, rs0, 1);
    rs0 += __shfl_xor_sync(0xffffffffu, rs0, 2);
    rs1 += __shfl_xor_sync(0xffffffffu, rs1, 1);
    rs1 += __shfl_xor_sync(0xffffffffu, rs1, 2);
    if (lx == 0) {
        atomicAdd(&den[wm + ly], rs0);
        atomicAdd(&den[wm + ly + 8], rs1);
    }
    __syncthreads();

    const float inv0 = 1.f / fmaxf(den[wm + ly], 1.f);
    const float inv1 = 1.f / fmaxf(den[wm + ly + 8], 1.f);
    #pragma unroll
    for (int ni = 0; ni < 8; ni++) {
        const int colg = h * D_ + wn2 + ni * 8 + 2 * lx;
        float* d0 = g_attn + (size_t)(qb * 64 + wm + ly) * (H_ * D_) + colg;
        float* d1 = g_attn + (size_t)(qb * 64 + wm + ly + 8) * (H_ * D_) + colg;
        *(float2*)d0 = make_float2(o[ni][0] * inv0, o[ni][1] * inv0);
        *(float2*)d1 = make_float2(o[ni][2] * inv1, o[ni][3] * inv1);
    }
}

// ---------------- launch ----------------
extern "C" void kernel_launch(void* const* d_in, const int* in_sizes, int n_in,
                              void* d_out, int out_size) {
    (void)in_sizes; (void)n_in; (void)out_size;
    const float* hs   = (const float*)d_in[0];
    const float* cosb = (const float*)d_in[1];
    const float* sinb = (const float*)d_in[2];
    const float* Wq   = (const float*)d_in[3];
    const float* Wk   = (const float*)d_in[4];
    const float* Wv   = (const float*)d_in[5];
    const float* Wg   = (const float*)d_in[6];
    const float* Wo   = (const float*)d_in[7];
    float* out = (float*)d_out;

    float *q, *k, *attn, *hsr, *wqr, *wkr, *wvr, *wor;
    cudaGetSymbolAddress((void**)&q,    g_q);
    cudaGetSymbolAddress((void**)&k,    g_k);
    cudaGetSymbolAddress((void**)&attn, g_attn);
    cudaGetSymbolAddress((void**)&hsr,  g_hsr);
    cudaGetSymbolAddress((void**)&wqr,  g_wqr);
    cudaGetSymbolAddress((void**)&wkr,  g_wkr);
    cudaGetSymbolAddress((void**)&wvr,  g_wvr);
    cudaGetSymbolAddress((void**)&wor,  g_wor);

    static cudaStream_t s1 = nullptr, s2 = nullptr, s3 = nullptr;
    static cudaEvent_t ev0, ev1, ev2, ev2a, ev3;
    if (!s1) {
        cudaStreamCreateWithFlags(&s1, cudaStreamNonBlocking);
        cudaStreamCreateWithFlags(&s2, cudaStreamNonBlocking);
        cudaStreamCreateWithFlags(&s3, cudaStreamNonBlocking);
        cudaEventCreateWithFlags(&ev0,  cudaEventDisableTiming);
        cudaEventCreateWithFlags(&ev1,  cudaEventDisableTiming);
        cudaEventCreateWithFlags(&ev2,  cudaEventDisableTiming);
        cudaEventCreateWithFlags(&ev2a, cudaEventDisableTiming);
        cudaEventCreateWithFlags(&ev3,  cudaEventDisableTiming);
    }

    cudaFuncSetAttribute(gemm_qkv, cudaFuncAttributeMaxDynamicSharedMemorySize, GEMM_SMEM3);
    cudaFuncSetAttribute(gemm_wo,  cudaFuncAttributeMaxDynamicSharedMemorySize, GEMM_SMEM3);
    cudaFuncSetAttribute(attn_kernel, cudaFuncAttributeMaxDynamicSharedMemorySize, ATTN_SMEM);

    cudaEventRecord(ev0, 0);

    // side stream 2: Wq preround
    cudaStreamWaitEvent(s2, ev0, 0);
    preround<<<(HID_*H_*D_)   / 1024, 256, 0, s2>>>(Wq, wqr);
    cudaEventRecord(ev2a, s2);

    // side stream 3: Wk, Wv, then Wo prerounds
    cudaStreamWaitEvent(s3, ev0, 0);
    preround<<<(HID_*HKV_*D_) / 1024, 256, 0, s3>>>(Wk, wkr);
    preround<<<(HID_*HKV_*D_) / 1024, 256, 0, s3>>>(Wv, wvr);
    cudaEventRecord(ev3, s3);
    preround<<<(H_*D_*HID_)   / 1024, 256, 0, s3>>>(Wo, wor);
    cudaEventRecord(ev2, s3);

    // side stream 1: gate path (exact fp32)
    cudaStreamWaitEvent(s1, ev0, 0);
    gate_proj<<<S_, 128, 0, s1>>>(hs, Wg);
    gcumsum_kernel<<<HKV_, 256, 0, s1>>>();
    cudaEventRecord(ev1, s1);

    // main stream
    preround<<<(S_*HID_) / 1024, 256>>>(hs, hsr);
    cudaStreamWaitEvent(0, ev2a, 0);
    cudaStreamWaitEvent(0, ev3, 0);
    gemm_qkv<<<dim3(24, S_ / BM), 256, GEMM_SMEM3>>>(hsr, wqr, wkr, wvr);
    rope_kernel<<<(S_*H_*64   + 255) / 256, 256>>>(q, cosb, sinb, H_);
    rope_kernel<<<(S_*HKV_*64 + 255) / 256, 256>>>(k, cosb, sinb, HKV_);

    cudaStreamWaitEvent(0, ev1, 0);
    attn_kernel<<<dim3(S_ / 64, H_), 256, ATTN_SMEM>>>();

    cudaStreamWaitEvent(0, ev2, 0);
    gemm_wo<<<dim3(HID_ / BN, S_ / BM), 256, GEMM_SMEM3>>>(attn, wor, out);
}

// round 9
// speedup vs baseline: 1.6499x; 1.3791x over previous
#include <cuda_runtime.h>
#include <cuda_fp16.h>
#include <math.h>

#define S_     2048
#define HID_   2048
#define H_     16
#define HKV_   4
#define D_     128
#define GROUPS_ 4
#define SCALE_ 0.08838834764831845f   // 128^-0.5
#define DECAY_CUT (-40.0f)

// ---------------- scratch (no cudaMalloc allowed) ----------------
__device__ float    g_q    [S_*H_*D_];
__device__ float    g_k    [S_*HKV_*D_];
__device__ float    g_v    [S_*HKV_*D_];
__device__ float    g_g    [S_*HKV_];
__device__ float    g_gc   [HKV_*S_];
__device__ __half   g_attnh[S_*H_*D_];          // fp16 attention output
__device__ __half   g_hsh  [S_*HID_];           // fp16 hidden states
__device__ unsigned g_wqp  [(HID_/2)*(H_*D_)];  // pair-interleaved fp16 weights
__device__ unsigned g_wkp  [(HID_/2)*(HKV_*D_)];
__device__ unsigned g_wvp  [(HID_/2)*(HKV_*D_)];
__device__ unsigned g_wop  [((H_*D_)/2)*HID_];

// ---------------- helpers ----------------
__device__ __forceinline__ unsigned packh2(float lo, float hi) {
    __half2 h = __floats2half2_rn(lo, hi);   // .x = lo (low half / lower address)
    return *(unsigned*)&h;
}
__device__ __forceinline__ void mma_f16(float c[4], const unsigned a[4], const unsigned b[2]) {
    asm volatile("mma.sync.aligned.m16n8k16.row.col.f32.f16.f16.f32 "
        "{%0,%1,%2,%3},{%4,%5,%6,%7},{%8,%9},{%0,%1,%2,%3};"
        : "+f"(c[0]), "+f"(c[1]), "+f"(c[2]), "+f"(c[3])
        : "r"(a[0]), "r"(a[1]), "r"(a[2]), "r"(a[3]), "r"(b[0]), "r"(b[1]));
}
__device__ __forceinline__ void mma_tf32(float c[4], const unsigned a[4], const unsigned b[2]) {
    asm volatile("mma.sync.aligned.m16n8k8.row.col.f32.tf32.tf32.f32 "
        "{%0,%1,%2,%3},{%4,%5,%6,%7},{%8,%9},{%0,%1,%2,%3};"
        : "+f"(c[0]), "+f"(c[1]), "+f"(c[2]), "+f"(c[3])
        : "r"(a[0]), "r"(a[1]), "r"(a[2]), "r"(a[3]), "r"(b[0]), "r"(b[1]));
}
__device__ __forceinline__ void split2(float x, unsigned& hi, unsigned& lo) {
    const unsigned h = __float_as_uint(x) & 0xffffe000u;
    hi = h;
    lo = __float_as_uint(x - __uint_as_float(h));
}
__device__ __forceinline__ void cpa16(void* sp, const void* gp) {
    unsigned s = (unsigned)__cvta_generic_to_shared(sp);
    asm volatile("cp.async.cg.shared.global [%0], [%1], 16;" :: "r"(s), "l"(gp));
}

// ---------------- f32 -> fp16 conversions ----------------
__global__ void tohalf_plain(const float* __restrict__ s, __half* __restrict__ d) {
    const size_t i = ((size_t)blockIdx.x * 256 + threadIdx.x) * 4;
    float4 v = *(const float4*)(s + i);
    uint2 u;
    u.x = packh2(v.x, v.y);
    u.y = packh2(v.z, v.w);
    *(uint2*)((unsigned*)d + i / 2) = u;
}
// W[K][N] f32 -> Wp[K/2][N] u32, Wp[kp][n] = pack(W[2kp][n], W[2kp+1][n])
__global__ void tohalf_pair(const float* __restrict__ W, unsigned* __restrict__ Wp, int N) {
    const int idx = blockIdx.x * 256 + threadIdx.x;
    const int nc4 = N / 4;
    const int kp = idx / nc4, c4 = (idx % nc4) * 4;
    const float4 w0 = *(const float4*)(W + (size_t)(2 * kp) * N + c4);
    const float4 w1 = *(const float4*)(W + (size_t)(2 * kp + 1) * N + c4);
    uint4 u;
    u.x = packh2(w0.x, w1.x);
    u.y = packh2(w0.y, w1.y);
    u.z = packh2(w0.z, w1.z);
    u.w = packh2(w0.w, w1.w);
    *(uint4*)(Wp + (size_t)kp * N + c4) = u;
}

// ---------------- fp16 tensor-core GEMM: 128x128 tile, BK=32, occ 2 ------
#define BM 128
#define BN 128
#define NK 64                       // 2048/32
#define PAH 20                      // A smem pitch (u32 pairs): banks verified
#define PBH 136                     // B smem pitch (u32): banks verified
#define STG_AH (128*PAH)            // 2560 u32
#define STG_BH (16*PBH)             // 2176 u32
#define GEMM_SMEMH (3*(STG_AH+STG_BH)*4)   // 56832 B

__device__ __forceinline__ void gemmh_issue(const __half* __restrict__ A,
        const unsigned* __restrict__ Bp, int N, int bm, int bn,
        unsigned* As, unsigned* Bs, int kt,
        int arow, int apair, int brow, int bcol) {
    unsigned* Ad = As + (kt % 3) * STG_AH;
    const unsigned* Ag = (const unsigned*)A + (size_t)(bm + arow) * 1024 + kt * 16 + apair;
    cpa16(Ad + arow * PAH + apair,     Ag);
    cpa16(Ad + arow * PAH + apair + 4, Ag + 4);
    unsigned* Bd = Bs + (kt % 3) * STG_BH;
    const unsigned* Bg = Bp + (size_t)(kt * 16 + brow) * N + bn + bcol;
    cpa16(Bd + brow * PBH + bcol,     Bg);
    cpa16(Bd + brow * PBH + bcol + 4, Bg + 4);
    asm volatile("cp.async.commit_group;");
}

__device__ __forceinline__ void gemmh_core(const __half* __restrict__ A,
        const unsigned* __restrict__ Bp, float* __restrict__ C,
        int N, int bm, int bn, unsigned* As, unsigned* Bs) {
    const int tid  = threadIdx.x;
    const int lane = tid & 31;
    const int warp = tid >> 5;
    const int ly = lane >> 2, lx = lane & 3;
    const int wm = (warp & 3) * 32;
    const int wn = (warp >> 2) * 64;
    const int arow = tid >> 1, apair = (tid & 1) * 8;
    const int brow = tid >> 4, bcol = (tid & 15) * 8;

    float acc[2][8][4];
    #pragma unroll
    for (int mi = 0; mi < 2; mi++)
        #pragma unroll
        for (int ni = 0; ni < 8; ni++)
            #pragma unroll
            for (int r = 0; r < 4; r++) acc[mi][ni][r] = 0.f;

    gemmh_issue(A, Bp, N, bm, bn, As, Bs, 0, arow, apair, brow, bcol);
    gemmh_issue(A, Bp, N, bm, bn, As, Bs, 1, arow, apair, brow, bcol);

    for (int kt = 0; kt < NK; kt++) {
        asm volatile("cp.async.wait_group 1;");
        __syncthreads();

        const unsigned* Ab = As + (kt % 3) * STG_AH;
        const unsigned* Bb = Bs + (kt % 3) * STG_BH;
        #pragma unroll
        for (int ks2 = 0; ks2 < 2; ks2++) {
            const int kp0 = ks2 * 8;
            unsigned af[2][4], bf[8][2];
            #pragma unroll
            for (int mi = 0; mi < 2; mi++) {
                const int r = wm + mi * 16 + ly;
                af[mi][0] = Ab[r * PAH + kp0 + lx];
                af[mi][1] = Ab[(r + 8) * PAH + kp0 + lx];
                af[mi][2] = Ab[r * PAH + kp0 + 4 + lx];
                af[mi][3] = Ab[(r + 8) * PAH + kp0 + 4 + lx];
            }
            #pragma unroll
            for (int ni = 0; ni < 8; ni++) {
                const int n = wn + ni * 8 + ly;
                bf[ni][0] = Bb[(kp0 + lx) * PBH + n];
                bf[ni][1] = Bb[(kp0 + 4 + lx) * PBH + n];
            }
            #pragma unroll
            for (int mi = 0; mi < 2; mi++)
                #pragma unroll
                for (int ni = 0; ni < 8; ni++)
                    mma_f16(acc[mi][ni], af[mi], bf[ni]);
        }
        __syncthreads();

        if (kt + 2 < NK)
            gemmh_issue(A, Bp, N, bm, bn, As, Bs, kt + 2, arow, apair, brow, bcol);
        else
            asm volatile("cp.async.commit_group;");
    }

    #pragma unroll
    for (int mi = 0; mi < 2; mi++) {
        const int r0 = bm + wm + mi * 16 + ly;
        #pragma unroll
        for (int ni = 0; ni < 8; ni++) {
            const int c0 = bn + wn + ni * 8 + 2 * lx;
            *(float2*)(C + (size_t)r0 * N + c0)       = make_float2(acc[mi][ni][0], acc[mi][ni][1]);
            *(float2*)(C + (size_t)(r0 + 8) * N + c0) = make_float2(acc[mi][ni][2], acc[mi][ni][3]);
        }
    }
}

__global__ void __launch_bounds__(256, 2) gemm_qkv(const __half* __restrict__ A) {
    extern __shared__ unsigned smu[];
    const int bx = blockIdx.x;
    const unsigned* Bp; float* Cm; int N, bn;
    if (bx < 16)      { Bp = g_wqp; Cm = g_q; N = 2048; bn = bx * 128; }
    else if (bx < 20) { Bp = g_wkp; Cm = g_k; N = 512;  bn = (bx - 16) * 128; }
    else              { Bp = g_wvp; Cm = g_v; N = 512;  bn = (bx - 20) * 128; }
    gemmh_core(A, Bp, Cm, N, blockIdx.y * BM, bn, smu, smu + 3 * STG_AH);
}

__global__ void __launch_bounds__(256, 2) gemm_wo(const __half* __restrict__ A,
        float* __restrict__ C) {
    extern __shared__ unsigned smu[];
    gemmh_core(A, g_wop, C, HID_, blockIdx.y * BM, blockIdx.x * BN, smu, smu + 3 * STG_AH);
}

// ---------------- gate projection (exact fp32) ----------------
__global__ void gate_proj(const float* __restrict__ hs, const float* __restrict__ Wg) {
    const int s = blockIdx.x;
    const int w = threadIdx.x >> 5, l = threadIdx.x & 31;
    const float* row = hs + (size_t)s * HID_;
    float acc = 0.f;
    for (int k = l; k < HID_; k += 32)
        acc = fmaf(row[k], Wg[k * HKV_ + w], acc);
    #pragma unroll
    for (int o = 16; o > 0; o >>= 1)
        acc += __shfl_down_sync(0xffffffffu, acc, o);
    if (l == 0) g_g[s * HKV_ + w] = acc;
}

// ---------------- log-sigmoid + parallel cumsum ----------------
__global__ void gcumsum_kernel() {
    __shared__ float ps[256];
    const int kv = blockIdx.x;
    const int t = threadIdx.x;
    float loc[8]; float s = 0.f;
    #pragma unroll
    for (int i = 0; i < 8; i++) {
        const float x = g_g[(t * 8 + i) * HKV_ + kv];
        const float ls = (x > 0.f) ? -log1pf(__expf(-x)) : x - log1pf(__expf(x));
        loc[i] = ls; s += ls;
    }
    ps[t] = s; __syncthreads();
    for (int o = 1; o < 256; o <<= 1) {
        const float v = (t >= o) ? ps[t - o] : 0.f;
        __syncthreads();
        ps[t] += v;
        __syncthreads();
    }
    float run = (t > 0) ? ps[t - 1] : 0.f;
    #pragma unroll
    for (int i = 0; i < 8; i++) {
        run += loc[i];
        g_gc[kv * S_ + t * 8 + i] = run;
    }
}

// ---------------- RoPE (in place) ----------------
__global__ void rope_kernel(float* __restrict__ x, const float* __restrict__ cosb,
                            const float* __restrict__ sinb, int nheads) {
    const int idx = blockIdx.x * blockDim.x + threadIdx.x;
    const int total = S_ * nheads * 64;
    if (idx >= total) return;
    const int d = idx % 64;
    const int h = (idx / 64) % nheads;
    const int s = idx / (64 * nheads);
    const float c  = cosb[s * 128 + d];
    const float sn = sinb[s * 128 + d];
    float* row = x + (size_t)s * nheads * 128 + h * 128;
    const float x0 = row[d], x1 = row[d + 64];
    row[d]      = x0 * c - x1 * sn;
    row[d + 64] = x1 * c + x0 * sn;
}

// ---------------- tensor-core causal power attention (3xTF32, R8) ---------
#define PQK 132
#define PV  136
#define PS  68
#define ATTN_SMEM ((2*64*PQK + 64*PV + 192) * 4)   // 103168 B

__global__ void __launch_bounds__(256, 2) attn_kernel() {
    extern __shared__ float sm[];
    float* Qs  = sm;
    float* Ks  = Qs + 64 * PQK;
    float* Ss  = Ks;                    // alias
    float* Vs  = Ks + 64 * PQK;
    float* Gq  = Vs + 64 * PV;
    float* Gk  = Gq + 64;
    float* den = Gk + 64;

    const int qb = gridDim.x - 1 - blockIdx.x;
    const int h = blockIdx.y, kv = h / GROUPS_;
    const int tid  = threadIdx.x;
    const int lane = tid & 31, warp = tid >> 5;
    const int ly = lane >> 2, lx = lane & 3;
    const int wm  = (warp & 3) * 16;
    const int wn  = (warp >> 2) * 32;
    const int wn2 = (warp >> 2) * 64;

    #pragma unroll
    for (int j = 0; j < 8; j++) {
        const int idx = j * 256 + tid;
        const int r = idx >> 5, d = (idx & 31) * 4;
        *(float4*)(Qs + r * PQK + d) =
            *(const float4*)(g_q + (size_t)(qb * 64 + r) * (H_ * D_) + h * D_ + d);
    }
    if (tid < 64) { Gq[tid] = g_gc[kv * S_ + qb * 64 + tid]; den[tid] = 0.f; }
    __syncthreads();

    const float gq0 = Gq[wm + ly];
    const float gq1 = Gq[wm + ly + 8];
    const float Gq0 = Gq[0];

    float o[8][4];
    #pragma unroll
    for (int ni = 0; ni < 8; ni++)
        #pragma unroll
        for (int r = 0; r < 4; r++) o[ni][r] = 0.f;
    float rs0 = 0.f, rs1 = 0.f;

    for (int kb = qb; kb >= 0; kb--) {
        if (kb < qb && Gq0 - g_gc[kv * S_ + kb * 64 + 63] < DECAY_CUT) break;
        __syncthreads();
        #pragma unroll
        for (int j = 0; j < 8; j++) {
            const int idx = j * 256 + tid;
            const int r = idx >> 5, d = (idx & 31) * 4;
            const size_t gbase = (size_t)(kb * 64 + r) * (HKV_ * D_) + kv * D_ + d;
            *(float4*)(Ks + r * PQK + d) = *(const float4*)(g_k + gbase);
            *(float4*)(Vs + r * PV  + d) = *(const float4*)(g_v + gbase);
        }
        if (tid < 64) Gk[tid] = g_gc[kv * S_ + kb * 64 + tid];
        __syncthreads();

        float c[4][4];
        #pragma unroll
        for (int ni = 0; ni < 4; ni++)
            #pragma unroll
            for (int r = 0; r < 4; r++) c[ni][r] = 0.f;
        #pragma unroll
        for (int ks = 0; ks < 128; ks += 8) {
            unsigned ah[4], al[4];
            const float* Qr = Qs + (wm + ly) * PQK + ks + lx;
            split2(Qr[0],           ah[0], al[0]);
            split2(Qr[8 * PQK],     ah[1], al[1]);
            split2(Qr[4],           ah[2], al[2]);
            split2(Qr[8 * PQK + 4], ah[3], al[3]);
            #pragma unroll
            for (int ni = 0; ni < 4; ni++) {
                unsigned bh[2], bl[2];
                const float* Kr = Ks + (wn + ni * 8 + ly) * PQK + ks + lx;
                split2(Kr[0], bh[0], bl[0]);
                split2(Kr[4], bh[1], bl[1]);
                mma_tf32(c[ni], ah, bh);
                mma_tf32(c[ni], al, bh);
                mma_tf32(c[ni], ah, bl);
            }
        }
        float gk0v[4], gk1v[4];
        #pragma unroll
        for (int ni = 0; ni < 4; ni++) {
            const int col = wn + ni * 8 + 2 * lx;
            gk0v[ni] = Gk[col];
            gk1v[ni] = Gk[col + 1];
        }
        __syncthreads();   // all warps done reading Ks -> safe to overwrite with S

        const int rg0 = qb * 64 + wm + ly;
        const int rg1 = rg0 + 8;
        #pragma unroll
        for (int ni = 0; ni < 4; ni++) {
            const int col = wn + ni * 8 + 2 * lx;
            const int cg  = kb * 64 + col;
            float t;
            t = c[ni][0] * SCALE_;
            const float v00 = (cg     <= rg0) ? t * t * __expf(gq0 - gk0v[ni]) : 0.f;
            t = c[ni][1] * SCALE_;
            const float v01 = (cg + 1 <= rg0) ? t * t * __expf(gq0 - gk1v[ni]) : 0.f;
            t = c[ni][2] * SCALE_;
            const float v10 = (cg     <= rg1) ? t * t * __expf(gq1 - gk0v[ni]) : 0.f;
            t = c[ni][3] * SCALE_;
            const float v11 = (cg + 1 <= rg1) ? t * t * __expf(gq1 - gk1v[ni]) : 0.f;
            rs0 += v00 + v01;
            rs1 += v10 + v11;
            *(float2*)(Ss + (wm + ly) * PS + col)     = make_float2(v00, v01);
            *(float2*)(Ss + (wm + ly + 8) * PS + col) = make_float2(v10, v11);
        }
        __syncthreads();

        #pragma unroll
        for (int ks = 0; ks < 64; ks += 8) {
            unsigned ah[4], al[4];
            const float* Sr = Ss + (wm + ly) * PS + ks + lx;
            split2(Sr[0],          ah[0], al[0]);
            split2(Sr[8 * PS],     ah[1], al[1]);
            split2(Sr[4],          ah[2], al[2]);
            split2(Sr[8 * PS + 4], ah[3], al[3]);
            #pragma unroll
            for (int ni = 0; ni < 8; ni++) {
                unsigned bh[2], bl[2];
                const float* Vr = Vs + (ks + lx) * PV + wn2 + ni * 8 + ly;
                split2(Vr[0],      bh[0], bl[0]);
                split2(Vr[4 * PV], bh[1], bl[1]);
                mma_tf32(o[ni], ah, bh);
                mma_tf32(o[ni], al, bh);
                mma_tf32(o[ni], ah, bl);
            }
        }
    }

    rs0 += __shfl_xor_sync(0xffffffffu, rs0, 1);
    rs0 += __shfl_xor_sync(0xffffffffu, rs0, 2);
    rs1 += __shfl_xor_sync(0xffffffffu, rs1, 1);
    rs1 += __shfl_xor_sync(0xffffffffu, rs1, 2);
    if (lx == 0) {
        atomicAdd(&den[wm + ly], rs0);
        atomicAdd(&den[wm + ly + 8], rs1);
    }
    __syncthreads();

    const float inv0 = 1.f / fmaxf(den[wm + ly], 1.f);
    const float inv1 = 1.f / fmaxf(den[wm + ly + 8], 1.f);
    unsigned* ah32 = (unsigned*)g_attnh;
    #pragma unroll
    for (int ni = 0; ni < 8; ni++) {
        const int colg = h * D_ + wn2 + ni * 8 + 2 * lx;   // even
        const size_t i0 = ((size_t)(qb * 64 + wm + ly) * (H_ * D_) + colg) / 2;
        const size_t i1 = ((size_t)(qb * 64 + wm + ly + 8) * (H_ * D_) + colg) / 2;
        ah32[i0] = packh2(o[ni][0] * inv0, o[ni][1] * inv0);
        ah32[i1] = packh2(o[ni][2] * inv1, o[ni][3] * inv1);
    }
}

// ---------------- launch ----------------
extern "C" void kernel_launch(void* const* d_in, const int* in_sizes, int n_in,
                              void* d_out, int out_size) {
    (void)in_sizes; (void)n_in; (void)out_size;
    const float* hs   = (const float*)d_in[0];
    const float* cosb = (const float*)d_in[1];
    const float* sinb = (const float*)d_in[2];
    const float* Wq   = (const float*)d_in[3];
    const float* Wk   = (const float*)d_in[4];
    const float* Wv   = (const float*)d_in[5];
    const float* Wg   = (const float*)d_in[6];
    const float* Wo   = (const float*)d_in[7];
    float* out = (float*)d_out;

    float *q, *k;
    __half *hsh, *attnh;
    unsigned *wqp, *wkp, *wvp, *wop;
    cudaGetSymbolAddress((void**)&q,     g_q);
    cudaGetSymbolAddress((void**)&k,     g_k);
    cudaGetSymbolAddress((void**)&hsh,   g_hsh);
    cudaGetSymbolAddress((void**)&attnh, g_attnh);
    cudaGetSymbolAddress((void**)&wqp,   g_wqp);
    cudaGetSymbolAddress((void**)&wkp,   g_wkp);
    cudaGetSymbolAddress((void**)&wvp,   g_wvp);
    cudaGetSymbolAddress((void**)&wop,   g_wop);

    static cudaStream_t s1 = nullptr, s2 = nullptr, s3 = nullptr;
    static cudaEvent_t ev0, ev1, ev2, ev2a, ev3;
    if (!s1) {
        cudaStreamCreateWithFlags(&s1, cudaStreamNonBlocking);
        cudaStreamCreateWithFlags(&s2, cudaStreamNonBlocking);
        cudaStreamCreateWithFlags(&s3, cudaStreamNonBlocking);
        cudaEventCreateWithFlags(&ev0,  cudaEventDisableTiming);
        cudaEventCreateWithFlags(&ev1,  cudaEventDisableTiming);
        cudaEventCreateWithFlags(&ev2,  cudaEventDisableTiming);
        cudaEventCreateWithFlags(&ev2a, cudaEventDisableTiming);
        cudaEventCreateWithFlags(&ev3,  cudaEventDisableTiming);
    }

    cudaFuncSetAttribute(gemm_qkv, cudaFuncAttributeMaxDynamicSharedMemorySize, GEMM_SMEMH);
    cudaFuncSetAttribute(gemm_wo,  cudaFuncAttributeMaxDynamicSharedMemorySize, GEMM_SMEMH);
    cudaFuncSetAttribute(attn_kernel, cudaFuncAttributeMaxDynamicSharedMemorySize, ATTN_SMEM);

    cudaEventRecord(ev0, 0);

    // side stream 2: Wq pair-pack
    cudaStreamWaitEvent(s2, ev0, 0);
    tohalf_pair<<<(HID_/2)*(H_*D_)/4/256, 256, 0, s2>>>(Wq, wqp, H_*D_);
    cudaEventRecord(ev2a, s2);

    // side stream 3: Wk, Wv, then Wo pair-packs
    cudaStreamWaitEvent(s3, ev0, 0);
    tohalf_pair<<<(HID_/2)*(HKV_*D_)/4/256, 256, 0, s3>>>(Wk, wkp, HKV_*D_);
    tohalf_pair<<<(HID_/2)*(HKV_*D_)/4/256, 256, 0, s3>>>(Wv, wvp, HKV_*D_);
    cudaEventRecord(ev3, s3);
    tohalf_pair<<<((H_*D_)/2)*HID_/4/256, 256, 0, s3>>>(Wo, wop, HID_);
    cudaEventRecord(ev2, s3);

    // side stream 1: gate path (exact fp32)
    cudaStreamWaitEvent(s1, ev0, 0);
    gate_proj<<<S_, 128, 0, s1>>>(hs, Wg);
    gcumsum_kernel<<<HKV_, 256, 0, s1>>>();
    cudaEventRecord(ev1, s1);

    // main stream
    tohalf_plain<<<(S_*HID_) / 1024, 256>>>(hs, hsh);
    cudaStreamWaitEvent(0, ev2a, 0);
    cudaStreamWaitEvent(0, ev3, 0);
    gemm_qkv<<<dim3(24, S_ / BM), 256, GEMM_SMEMH>>>(hsh);
    rope_kernel<<<(S_*H_*64   + 255) / 256, 256>>>(q, cosb, sinb, H_);
    rope_kernel<<<(S_*HKV_*64 + 255) / 256, 256>>>(k, cosb, sinb, HKV_);

    cudaStreamWaitEvent(0, ev1, 0);
    attn_kernel<<<dim3(S_ / 64, H_), 256, ATTN_SMEM>>>();

    cudaStreamWaitEvent(0, ev2, 0);
    gemm_wo<<<dim3(HID_ / BN, S_ / BM), 256, GEMM_SMEMH>>>(attnh, out);
}

// round 10
// speedup vs baseline: 1.7812x; 1.0796x over previous
#include <cuda_runtime.h>
#include <cuda_fp16.h>
#include <math.h>

#define S_     2048
#define HID_   2048
#define H_     16
#define HKV_   4
#define D_     128
#define GROUPS_ 4
#define SCALE_ 0.08838834764831845f   // 128^-0.5
#define DECAY_CUT (-40.0f)
#define SSCALE 512.0f
#define INV_SSCALE (1.0f/512.0f)

// ---------------- scratch (no cudaMalloc allowed) ----------------
__device__ float    g_q    [S_*H_*D_];          // unroped; rope applied in attn loader
__device__ float    g_k    [S_*HKV_*D_];
__device__ float    g_v    [S_*HKV_*D_];
__device__ float    g_g    [S_*HKV_];
__device__ float    g_gc   [HKV_*S_];
__device__ __half   g_attnh[S_*H_*D_];
__device__ __half   g_hsh  [S_*HID_];
__device__ unsigned g_wqp  [(HID_/2)*(H_*D_)];
__device__ unsigned g_wkp  [(HID_/2)*(HKV_*D_)];
__device__ unsigned g_wvp  [(HID_/2)*(HKV_*D_)];
__device__ unsigned g_wop  [((H_*D_)/2)*HID_];

// ---------------- helpers ----------------
__device__ __forceinline__ unsigned packh2(float lo, float hi) {
    __half2 h = __floats2half2_rn(lo, hi);
    return *(unsigned*)&h;
}
// fp16 hi/lo split of a float pair (a -> low half, b -> high half)
__device__ __forceinline__ unsigned sp_hi(float a, float b, unsigned& lo) {
    const __half ha = __float2half_rn(a), hb = __float2half_rn(b);
    lo = packh2(a - __half2float(ha), b - __half2float(hb));
    const __half2 hh = __halves2half2(ha, hb);
    return *(unsigned*)&hh;
}
__device__ __forceinline__ void mma_f16(float c[4], const unsigned a[4], const unsigned b[2]) {
    asm volatile("mma.sync.aligned.m16n8k16.row.col.f32.f16.f16.f32 "
        "{%0,%1,%2,%3},{%4,%5,%6,%7},{%8,%9},{%0,%1,%2,%3};"
        : "+f"(c[0]), "+f"(c[1]), "+f"(c[2]), "+f"(c[3])
        : "r"(a[0]), "r"(a[1]), "r"(a[2]), "r"(a[3]), "r"(b[0]), "r"(b[1]));
}
__device__ __forceinline__ void cpa16(void* sp, const void* gp) {
    unsigned s = (unsigned)__cvta_generic_to_shared(sp);
    asm volatile("cp.async.cg.shared.global [%0], [%1], 16;" :: "r"(s), "l"(gp));
}

// ---------------- f32 -> fp16 conversions ----------------
__global__ void tohalf_plain(const float* __restrict__ s, __half* __restrict__ d) {
    const size_t i = ((size_t)blockIdx.x * 256 + threadIdx.x) * 4;
    float4 v = *(const float4*)(s + i);
    uint2 u;
    u.x = packh2(v.x, v.y);
    u.y = packh2(v.z, v.w);
    *(uint2*)((unsigned*)d + i / 2) = u;
}
__global__ void tohalf_pair(const float* __restrict__ W, unsigned* __restrict__ Wp, int N) {
    const int idx = blockIdx.x * 256 + threadIdx.x;
    const int nc4 = N / 4;
    const int kp = idx / nc4, c4 = (idx % nc4) * 4;
    const float4 w0 = *(const float4*)(W + (size_t)(2 * kp) * N + c4);
    const float4 w1 = *(const float4*)(W + (size_t)(2 * kp + 1) * N + c4);
    uint4 u;
    u.x = packh2(w0.x, w1.x);
    u.y = packh2(w0.y, w1.y);
    u.z = packh2(w0.z, w1.z);
    u.w = packh2(w0.w, w1.w);
    *(uint4*)(Wp + (size_t)kp * N + c4) = u;
}

// ---------------- fp16 tensor-core GEMM (R9, proven) ----------------
#define BM 128
#define BN 128
#define NK 64
#define PAH 20
#define PBH 136
#define STG_AH (128*PAH)
#define STG_BH (16*PBH)
#define GEMM_SMEMH (3*(STG_AH+STG_BH)*4)

__device__ __forceinline__ void gemmh_issue(const __half* __restrict__ A,
        const unsigned* __restrict__ Bp, int N, int bm, int bn,
        unsigned* As, unsigned* Bs, int kt,
        int arow, int apair, int brow, int bcol) {
    unsigned* Ad = As + (kt % 3) * STG_AH;
    const unsigned* Ag = (const unsigned*)A + (size_t)(bm + arow) * 1024 + kt * 16 + apair;
    cpa16(Ad + arow * PAH + apair,     Ag);
    cpa16(Ad + arow * PAH + apair + 4, Ag + 4);
    unsigned* Bd = Bs + (kt % 3) * STG_BH;
    const unsigned* Bg = Bp + (size_t)(kt * 16 + brow) * N + bn + bcol;
    cpa16(Bd + brow * PBH + bcol,     Bg);
    cpa16(Bd + brow * PBH + bcol + 4, Bg + 4);
    asm volatile("cp.async.commit_group;");
}

__device__ __forceinline__ void gemmh_core(const __half* __restrict__ A,
        const unsigned* __restrict__ Bp, float* __restrict__ C,
        int N, int bm, int bn, unsigned* As, unsigned* Bs) {
    const int tid  = threadIdx.x;
    const int lane = tid & 31;
    const int warp = tid >> 5;
    const int ly = lane >> 2, lx = lane & 3;
    const int wm = (warp & 3) * 32;
    const int wn = (warp >> 2) * 64;
    const int arow = tid >> 1, apair = (tid & 1) * 8;
    const int brow = tid >> 4, bcol = (tid & 15) * 8;

    float acc[2][8][4];
    #pragma unroll
    for (int mi = 0; mi < 2; mi++)
        #pragma unroll
        for (int ni = 0; ni < 8; ni++)
            #pragma unroll
            for (int r = 0; r < 4; r++) acc[mi][ni][r] = 0.f;

    gemmh_issue(A, Bp, N, bm, bn, As, Bs, 0, arow, apair, brow, bcol);
    gemmh_issue(A, Bp, N, bm, bn, As, Bs, 1, arow, apair, brow, bcol);

    for (int kt = 0; kt < NK; kt++) {
        asm volatile("cp.async.wait_group 1;");
        __syncthreads();

        const unsigned* Ab = As + (kt % 3) * STG_AH;
        const unsigned* Bb = Bs + (kt % 3) * STG_BH;
        #pragma unroll
        for (int ks2 = 0; ks2 < 2; ks2++) {
            const int kp0 = ks2 * 8;
            unsigned af[2][4], bf[8][2];
            #pragma unroll
            for (int mi = 0; mi < 2; mi++) {
                const int r = wm + mi * 16 + ly;
                af[mi][0] = Ab[r * PAH + kp0 + lx];
                af[mi][1] = Ab[(r + 8) * PAH + kp0 + lx];
                af[mi][2] = Ab[r * PAH + kp0 + 4 + lx];
                af[mi][3] = Ab[(r + 8) * PAH + kp0 + 4 + lx];
            }
            #pragma unroll
            for (int ni = 0; ni < 8; ni++) {
                const int n = wn + ni * 8 + ly;
                bf[ni][0] = Bb[(kp0 + lx) * PBH + n];
                bf[ni][1] = Bb[(kp0 + 4 + lx) * PBH + n];
            }
            #pragma unroll
            for (int mi = 0; mi < 2; mi++)
                #pragma unroll
                for (int ni = 0; ni < 8; ni++)
                    mma_f16(acc[mi][ni], af[mi], bf[ni]);
        }
        __syncthreads();

        if (kt + 2 < NK)
            gemmh_issue(A, Bp, N, bm, bn, As, Bs, kt + 2, arow, apair, brow, bcol);
        else
            asm volatile("cp.async.commit_group;");
    }

    #pragma unroll
    for (int mi = 0; mi < 2; mi++) {
        const int r0 = bm + wm + mi * 16 + ly;
        #pragma unroll
        for (int ni = 0; ni < 8; ni++) {
            const int c0 = bn + wn + ni * 8 + 2 * lx;
            *(float2*)(C + (size_t)r0 * N + c0)       = make_float2(acc[mi][ni][0], acc[mi][ni][1]);
            *(float2*)(C + (size_t)(r0 + 8) * N + c0) = make_float2(acc[mi][ni][2], acc[mi][ni][3]);
        }
    }
}

__global__ void __launch_bounds__(256, 2) gemm_qkv(const __half* __restrict__ A) {
    extern __shared__ unsigned smu[];
    const int bx = blockIdx.x;
    const unsigned* Bp; float* Cm; int N, bn;
    if (bx < 16)      { Bp = g_wqp; Cm = g_q; N = 2048; bn = bx * 128; }
    else if (bx < 20) { Bp = g_wkp; Cm = g_k; N = 512;  bn = (bx - 16) * 128; }
    else              { Bp = g_wvp; Cm = g_v; N = 512;  bn = (bx - 20) * 128; }
    gemmh_core(A, Bp, Cm, N, blockIdx.y * BM, bn, smu, smu + 3 * STG_AH);
}

__global__ void __launch_bounds__(256, 2) gemm_wo(const __half* __restrict__ A,
        float* __restrict__ C) {
    extern __shared__ unsigned smu[];
    gemmh_core(A, g_wop, C, HID_, blockIdx.y * BM, blockIdx.x * BN, smu, smu + 3 * STG_AH);
}

// ---------------- gate projection (exact fp32) ----------------
__global__ void gate_proj(const float* __restrict__ hs, const float* __restrict__ Wg) {
    const int s = blockIdx.x;
    const int w = threadIdx.x >> 5, l = threadIdx.x & 31;
    const float* row = hs + (size_t)s * HID_;
    float acc = 0.f;
    for (int k = l; k < HID_; k += 32)
        acc = fmaf(row[k], Wg[k * HKV_ + w], acc);
    #pragma unroll
    for (int o = 16; o > 0; o >>= 1)
        acc += __shfl_down_sync(0xffffffffu, acc, o);
    if (l == 0) g_g[s * HKV_ + w] = acc;
}

// ---------------- log-sigmoid + parallel cumsum ----------------
__global__ void gcumsum_kernel() {
    __shared__ float ps[256];
    const int kv = blockIdx.x;
    const int t = threadIdx.x;
    float loc[8]; float s = 0.f;
    #pragma unroll
    for (int i = 0; i < 8; i++) {
        const float x = g_g[(t * 8 + i) * HKV_ + kv];
        const float ls = (x > 0.f) ? -log1pf(__expf(-x)) : x - log1pf(__expf(x));
        loc[i] = ls; s += ls;
    }
    ps[t] = s; __syncthreads();
    for (int o = 1; o < 256; o <<= 1) {
        const float v = (t >= o) ? ps[t - o] : 0.f;
        __syncthreads();
        ps[t] += v;
        __syncthreads();
    }
    float run = (t > 0) ? ps[t - 1] : 0.f;
    #pragma unroll
    for (int i = 0; i < 8; i++) {
        run += loc[i];
        g_gc[kv * S_ + t * 8 + i] = run;
    }
}

// ---------------- fp16-split tensor-core power attention -----------------
// Operands pre-split (hi/lo fp16) in smem; rope fused into Q/K loaders.
// S staged x512 to dodge fp16 subnormal flush; rowsums exact f32.
#define PQ2 68     // Q/K pitch in u32 k-pairs (%32==4)
#define PS2 36     // S pitch in u32 j-pairs  (%32==4)
#define PV2 136    // V pitch in u32 (n index) (%32==8)
#define ATTN_SMEM ((4*64*PQ2 + 2*32*PV2 + 192) * 4)   // 105216 B

__global__ void __launch_bounds__(256, 2) attn_kernel(
        const float* __restrict__ cosb, const float* __restrict__ sinb) {
    extern __shared__ unsigned smu[];
    unsigned* Qhi = smu;                    // [64][PQ2]
    unsigned* Qlo = Qhi + 64 * PQ2;
    unsigned* Khi = Qlo + 64 * PQ2;         // [64][PQ2]; S aliases after QK
    unsigned* Klo = Khi + 64 * PQ2;
    unsigned* Vhi = Klo + 64 * PQ2;         // [32][PV2]
    unsigned* Vlo = Vhi + 32 * PV2;
    float* Gq  = (float*)(Vlo + 32 * PV2);
    float* Gk  = Gq + 64;
    float* den = Gk + 64;
    unsigned* Shi = Khi;                    // [64][PS2] alias
    unsigned* Slo = Klo;

    const int qb = gridDim.x - 1 - blockIdx.x;
    const int h = blockIdx.y, kv = h / GROUPS_;
    const int tid  = threadIdx.x;
    const int lane = tid & 31, warp = tid >> 5;
    const int ly = lane >> 2, lx = lane & 3;
    const int wm  = (warp & 3) * 16;
    const int wn  = (warp >> 2) * 32;
    const int wn2 = (warp >> 2) * 64;

    // ---- load Q tile with fused rope + fp16 split ----
    #pragma unroll
    for (int j = 0; j < 8; j++) {
        const int idx = j * 256 + tid;
        const int r = idx >> 5, d0 = (idx & 31) * 4;
        const int srow = qb * 64 + r;
        const float* base = g_q + (size_t)srow * (H_ * D_) + h * D_;
        const float4 x  = *(const float4*)(base + d0);
        const float4 y  = *(const float4*)(base + (d0 ^ 64));
        const float4 c4 = *(const float4*)(cosb + srow * 128 + d0);
        const float4 s4 = *(const float4*)(sinb + srow * 128 + d0);
        const float sg = (d0 < 64) ? -1.f : 1.f;
        const float r0 = x.x * c4.x + sg * y.x * s4.x;
        const float r1 = x.y * c4.y + sg * y.y * s4.y;
        const float r2 = x.z * c4.z + sg * y.z * s4.z;
        const float r3 = x.w * c4.w + sg * y.w * s4.w;
        unsigned l0, l1;
        const unsigned h0 = sp_hi(r0, r1, l0);
        const unsigned h1 = sp_hi(r2, r3, l1);
        Qhi[r * PQ2 + d0 / 2]     = h0;
        Qhi[r * PQ2 + d0 / 2 + 1] = h1;
        Qlo[r * PQ2 + d0 / 2]     = l0;
        Qlo[r * PQ2 + d0 / 2 + 1] = l1;
    }
    if (tid < 64) { Gq[tid] = g_gc[kv * S_ + qb * 64 + tid]; den[tid] = 0.f; }
    __syncthreads();

    const float gq0 = Gq[wm + ly];
    const float gq1 = Gq[wm + ly + 8];
    const float Gq0 = Gq[0];

    float o[8][4];
    #pragma unroll
    for (int ni = 0; ni < 8; ni++)
        #pragma unroll
        for (int r = 0; r < 4; r++) o[ni][r] = 0.f;
    float rs0 = 0.f, rs1 = 0.f;

    for (int kb = qb; kb >= 0; kb--) {
        if (kb < qb && Gq0 - g_gc[kv * S_ + kb * 64 + 63] < DECAY_CUT) break;
        __syncthreads();   // prev SV done reading S/V

        // ---- K tile: rope + split ----
        #pragma unroll
        for (int j = 0; j < 8; j++) {
            const int idx = j * 256 + tid;
            const int r = idx >> 5, d0 = (idx & 31) * 4;
            const int srow = kb * 64 + r;
            const float* base = g_k + (size_t)srow * (HKV_ * D_) + kv * D_;
            const float4 x  = *(const float4*)(base + d0);
            const float4 y  = *(const float4*)(base + (d0 ^ 64));
            const float4 c4 = *(const float4*)(cosb + srow * 128 + d0);
            const float4 s4 = *(const float4*)(sinb + srow * 128 + d0);
            const float sg = (d0 < 64) ? -1.f : 1.f;
            const float r0 = x.x * c4.x + sg * y.x * s4.x;
            const float r1 = x.y * c4.y + sg * y.y * s4.y;
            const float r2 = x.z * c4.z + sg * y.z * s4.z;
            const float r3 = x.w * c4.w + sg * y.w * s4.w;
            unsigned l0, l1;
            const unsigned h0 = sp_hi(r0, r1, l0);
            const unsigned h1 = sp_hi(r2, r3, l1);
            Khi[r * PQ2 + d0 / 2]     = h0;
            Khi[r * PQ2 + d0 / 2 + 1] = h1;
            Klo[r * PQ2 + d0 / 2]     = l0;
            Klo[r * PQ2 + d0 / 2 + 1] = l1;
        }
        // ---- V tile: pack k-pairs across rows + split ----
        #pragma unroll
        for (int j = 0; j < 4; j++) {
            const int idx = j * 256 + tid;
            const int kp = idx >> 5, n0 = (idx & 31) * 4;
            const size_t b0 = (size_t)(kb * 64 + 2 * kp) * (HKV_ * D_) + kv * D_ + n0;
            const float4 v0 = *(const float4*)(g_v + b0);
            const float4 v1 = *(const float4*)(g_v + b0 + HKV_ * D_);
            unsigned l0, l1, l2, l3;
            Vhi[kp * PV2 + n0 + 0] = sp_hi(v0.x, v1.x, l0);
            Vhi[kp * PV2 + n0 + 1] = sp_hi(v0.y, v1.y, l1);
            Vhi[kp * PV2 + n0 + 2] = sp_hi(v0.z, v1.z, l2);
            Vhi[kp * PV2 + n0 + 3] = sp_hi(v0.w, v1.w, l3);
            Vlo[kp * PV2 + n0 + 0] = l0;
            Vlo[kp * PV2 + n0 + 1] = l1;
            Vlo[kp * PV2 + n0 + 2] = l2;
            Vlo[kp * PV2 + n0 + 3] = l3;
        }
        if (tid < 64) Gk[tid] = g_gc[kv * S_ + kb * 64 + tid];
        __syncthreads();

        // ---- S = QK^T (3x fp16-split mma, k16) ----
        float c[4][4];
        #pragma unroll
        for (int ni = 0; ni < 4; ni++)
            #pragma unroll
            for (int r = 0; r < 4; r++) c[ni][r] = 0.f;
        #pragma unroll
        for (int ks2 = 0; ks2 < 8; ks2++) {
            const int kp0 = ks2 * 8;
            unsigned ah[4], al[4];
            const int r = wm + ly;
            ah[0] = Qhi[r * PQ2 + kp0 + lx];
            ah[1] = Qhi[(r + 8) * PQ2 + kp0 + lx];
            ah[2] = Qhi[r * PQ2 + kp0 + 4 + lx];
            ah[3] = Qhi[(r + 8) * PQ2 + kp0 + 4 + lx];
            al[0] = Qlo[r * PQ2 + kp0 + lx];
            al[1] = Qlo[(r + 8) * PQ2 + kp0 + lx];
            al[2] = Qlo[r * PQ2 + kp0 + 4 + lx];
            al[3] = Qlo[(r + 8) * PQ2 + kp0 + 4 + lx];
            #pragma unroll
            for (int ni = 0; ni < 4; ni++) {
                const int n = wn + ni * 8 + ly;
                unsigned bh[2], bl[2];
                bh[0] = Khi[n * PQ2 + kp0 + lx];
                bh[1] = Khi[n * PQ2 + kp0 + 4 + lx];
                bl[0] = Klo[n * PQ2 + kp0 + lx];
                bl[1] = Klo[n * PQ2 + kp0 + 4 + lx];
                mma_f16(c[ni], ah, bh);
                mma_f16(c[ni], al, bh);
                mma_f16(c[ni], ah, bl);
            }
        }
        float gk0v[4], gk1v[4];
        #pragma unroll
        for (int ni = 0; ni < 4; ni++) {
            const int col = wn + ni * 8 + 2 * lx;
            gk0v[ni] = Gk[col];
            gk1v[ni] = Gk[col + 1];
        }
        __syncthreads();   // all warps done reading K -> S may overwrite

        // ---- mask, scale^2, decay; rowsums; stage S (x512, split) ----
        const int rg0 = qb * 64 + wm + ly;
        const int rg1 = rg0 + 8;
        #pragma unroll
        for (int ni = 0; ni < 4; ni++) {
            const int col = wn + ni * 8 + 2 * lx;
            const int cg  = kb * 64 + col;
            float t;
            t = c[ni][0] * SCALE_;
            const float v00 = (cg     <= rg0) ? t * t * __expf(gq0 - gk0v[ni]) : 0.f;
            t = c[ni][1] * SCALE_;
            const float v01 = (cg + 1 <= rg0) ? t * t * __expf(gq0 - gk1v[ni]) : 0.f;
            t = c[ni][2] * SCALE_;
            const float v10 = (cg     <= rg1) ? t * t * __expf(gq1 - gk0v[ni]) : 0.f;
            t = c[ni][3] * SCALE_;
            const float v11 = (cg + 1 <= rg1) ? t * t * __expf(gq1 - gk1v[ni]) : 0.f;
            rs0 += v00 + v01;
            rs1 += v10 + v11;
            const int sp = wn / 2 + 4 * ni + lx;
            unsigned l0, l1;
            Shi[(wm + ly) * PS2 + sp]     = sp_hi(v00 * SSCALE, v01 * SSCALE, l0);
            Shi[(wm + ly + 8) * PS2 + sp] = sp_hi(v10 * SSCALE, v11 * SSCALE, l1);
            Slo[(wm + ly) * PS2 + sp]     = l0;
            Slo[(wm + ly + 8) * PS2 + sp] = l1;
        }
        __syncthreads();

        // ---- O += S @ V (3x fp16-split mma, k16) ----
        #pragma unroll
        for (int ks2 = 0; ks2 < 4; ks2++) {
            const int jp0 = ks2 * 8;
            unsigned ah[4], al[4];
            const int r = wm + ly;
            ah[0] = Shi[r * PS2 + jp0 + lx];
            ah[1] = Shi[(r + 8) * PS2 + jp0 + lx];
            ah[2] = Shi[r * PS2 + jp0 + 4 + lx];
            ah[3] = Shi[(r + 8) * PS2 + jp0 + 4 + lx];
            al[0] = Slo[r * PS2 + jp0 + lx];
            al[1] = Slo[(r + 8) * PS2 + jp0 + lx];
            al[2] = Slo[r * PS2 + jp0 + 4 + lx];
            al[3] = Slo[(r + 8) * PS2 + jp0 + 4 + lx];
            #pragma unroll
            for (int ni = 0; ni < 8; ni++) {
                const int n = wn2 + ni * 8 + ly;
                unsigned bh[2], bl[2];
                bh[0] = Vhi[(jp0 + lx) * PV2 + n];
                bh[1] = Vhi[(jp0 + 4 + lx) * PV2 + n];
                bl[0] = Vlo[(jp0 + lx) * PV2 + n];
                bl[1] = Vlo[(jp0 + 4 + lx) * PV2 + n];
                mma_f16(o[ni], ah, bh);
                mma_f16(o[ni], al, bh);
                mma_f16(o[ni], ah, bl);
            }
        }
    }

    rs0 += __shfl_xor_sync(0xffffffffu, rs0, 1);
    rs0 += __shfl_xor_sync(0xffffffffu, rs0, 2);
    rs1 += __shfl_xor_sync(0xffffffffu, rs1, 1);
    rs1 += __shfl_xor_sync(0xffffffffu, rs1, 2);
    if (lx == 0) {
        atomicAdd(&den[wm + ly], rs0);
        atomicAdd(&den[wm + ly + 8], rs1);
    }
    __syncthreads();

    const float inv0 = INV_SSCALE / fmaxf(den[wm + ly], 1.f);
    const float inv1 = INV_SSCALE / fmaxf(den[wm + ly + 8], 1.f);
    unsigned* ah32 = (unsigned*)g_attnh;
    #pragma unroll
    for (int ni = 0; ni < 8; ni++) {
        const int colg = h * D_ + wn2 + ni * 8 + 2 * lx;
        const size_t i0 = ((size_t)(qb * 64 + wm + ly) * (H_ * D_) + colg) / 2;
        const size_t i1 = ((size_t)(qb * 64 + wm + ly + 8) * (H_ * D_) + colg) / 2;
        ah32[i0] = packh2(o[ni][0] * inv0, o[ni][1] * inv0);
        ah32[i1] = packh2(o[ni][2] * inv1, o[ni][3] * inv1);
    }
}

// ---------------- launch ----------------
extern "C" void kernel_launch(void* const* d_in, const int* in_sizes, int n_in,
                              void* d_out, int out_size) {
    (void)in_sizes; (void)n_in; (void)out_size;
    const float* hs   = (const float*)d_in[0];
    const float* cosb = (const float*)d_in[1];
    const float* sinb = (const float*)d_in[2];
    const float* Wq   = (const float*)d_in[3];
    const float* Wk   = (const float*)d_in[4];
    const float* Wv   = (const float*)d_in[5];
    const float* Wg   = (const float*)d_in[6];
    const float* Wo   = (const float*)d_in[7];
    float* out = (float*)d_out;

    __half *hsh, *attnh;
    unsigned *wqp, *wkp, *wvp, *wop;
    cudaGetSymbolAddress((void**)&hsh,   g_hsh);
    cudaGetSymbolAddress((void**)&attnh, g_attnh);
    cudaGetSymbolAddress((void**)&wqp,   g_wqp);
    cudaGetSymbolAddress((void**)&wkp,   g_wkp);
    cudaGetSymbolAddress((void**)&wvp,   g_wvp);
    cudaGetSymbolAddress((void**)&wop,   g_wop);

    static cudaStream_t s1 = nullptr, s2 = nullptr, s3 = nullptr;
    static cudaEvent_t ev0, ev1, ev2, ev2a, ev3;
    if (!s1) {
        cudaStreamCreateWithFlags(&s1, cudaStreamNonBlocking);
        cudaStreamCreateWithFlags(&s2, cudaStreamNonBlocking);
        cudaStreamCreateWithFlags(&s3, cudaStreamNonBlocking);
        cudaEventCreateWithFlags(&ev0,  cudaEventDisableTiming);
        cudaEventCreateWithFlags(&ev1,  cudaEventDisableTiming);
        cudaEventCreateWithFlags(&ev2,  cudaEventDisableTiming);
        cudaEventCreateWithFlags(&ev2a, cudaEventDisableTiming);
        cudaEventCreateWithFlags(&ev3,  cudaEventDisableTiming);
    }

    cudaFuncSetAttribute(gemm_qkv, cudaFuncAttributeMaxDynamicSharedMemorySize, GEMM_SMEMH);
    cudaFuncSetAttribute(gemm_wo,  cudaFuncAttributeMaxDynamicSharedMemorySize, GEMM_SMEMH);
    cudaFuncSetAttribute(attn_kernel, cudaFuncAttributeMaxDynamicSharedMemorySize, ATTN_SMEM);

    cudaEventRecord(ev0, 0);

    // side stream 2: Wq pair-pack
    cudaStreamWaitEvent(s2, ev0, 0);
    tohalf_pair<<<(HID_/2)*(H_*D_)/4/256, 256, 0, s2>>>(Wq, wqp, H_*D_);
    cudaEventRecord(ev2a, s2);

    // side stream 3: Wk, Wv, then Wo pair-packs
    cudaStreamWaitEvent(s3, ev0, 0);
    tohalf_pair<<<(HID_/2)*(HKV_*D_)/4/256, 256, 0, s3>>>(Wk, wkp, HKV_*D_);
    tohalf_pair<<<(HID_/2)*(HKV_*D_)/4/256, 256, 0, s3>>>(Wv, wvp, HKV_*D_);
    cudaEventRecord(ev3, s3);
    tohalf_pair<<<((H_*D_)/2)*HID_/4/256, 256, 0, s3>>>(Wo, wop, HID_);
    cudaEventRecord(ev2, s3);

    // side stream 1: gate path (exact fp32)
    cudaStreamWaitEvent(s1, ev0, 0);
    gate_proj<<<S_, 128, 0, s1>>>(hs, Wg);
    gcumsum_kernel<<<HKV_, 256, 0, s1>>>();
    cudaEventRecord(ev1, s1);

    // main stream
    tohalf_plain<<<(S_*HID_) / 1024, 256>>>(hs, hsh);
    cudaStreamWaitEvent(0, ev2a, 0);
    cudaStreamWaitEvent(0, ev3, 0);
    gemm_qkv<<<dim3(24, S_ / BM), 256, GEMM_SMEMH>>>(hsh);

    cudaStreamWaitEvent(0, ev1, 0);
    attn_kernel<<<dim3(S_ / 64, H_), 256, ATTN_SMEM>>>(cosb, sinb);

    cudaStreamWaitEvent(0, ev2, 0);
    gemm_wo<<<dim3(HID_ / BN, S_ / BM), 256, GEMM_SMEMH>>>(attnh, out);
}

// round 11
// speedup vs baseline: 1.8019x; 1.0116x over previous
#include <cuda_runtime.h>
#include <cuda_fp16.h>
#include <math.h>

#define S_     2048
#define HID_   2048
#define H_     16
#define HKV_   4
#define D_     128
#define GROUPS_ 4
#define SCALE_ 0.08838834764831845f   // 128^-0.5
#define DECAY_CUT (-40.0f)
#define SSCALE 512.0f
#define INV_SSCALE (1.0f/512.0f)

// ---------------- scratch (no cudaMalloc allowed) ----------------
__device__ float    g_q    [S_*H_*D_];          // unroped; rope applied in attn loader
__device__ float    g_k    [S_*HKV_*D_];
__device__ float    g_v    [S_*HKV_*D_];
__device__ float    g_g    [S_*HKV_];
__device__ float    g_gc   [HKV_*S_];
__device__ __half   g_attnh[S_*H_*D_];
__device__ __half   g_hsh  [S_*HID_];
__device__ unsigned g_wqp  [(HID_/2)*(H_*D_)];
__device__ unsigned g_wkp  [(HID_/2)*(HKV_*D_)];
__device__ unsigned g_wvp  [(HID_/2)*(HKV_*D_)];
__device__ unsigned g_wop  [((H_*D_)/2)*HID_];

// ---------------- helpers ----------------
__device__ __forceinline__ unsigned packh2(float lo, float hi) {
    __half2 h = __floats2half2_rn(lo, hi);
    return *(unsigned*)&h;
}
__device__ __forceinline__ unsigned sp_hi(float a, float b, unsigned& lo) {
    const __half ha = __float2half_rn(a), hb = __float2half_rn(b);
    lo = packh2(a - __half2float(ha), b - __half2float(hb));
    const __half2 hh = __halves2half2(ha, hb);
    return *(unsigned*)&hh;
}
__device__ __forceinline__ void mma_f16(float c[4], const unsigned a[4], const unsigned b[2]) {
    asm volatile("mma.sync.aligned.m16n8k16.row.col.f32.f16.f16.f32 "
        "{%0,%1,%2,%3},{%4,%5,%6,%7},{%8,%9},{%0,%1,%2,%3};"
        : "+f"(c[0]), "+f"(c[1]), "+f"(c[2]), "+f"(c[3])
        : "r"(a[0]), "r"(a[1]), "r"(a[2]), "r"(a[3]), "r"(b[0]), "r"(b[1]));
}
__device__ __forceinline__ void ldsm_x4(unsigned r[4], unsigned saddr) {
    asm volatile("ldmatrix.sync.aligned.m8n8.x4.shared.b16 {%0,%1,%2,%3}, [%4];"
        : "=r"(r[0]), "=r"(r[1]), "=r"(r[2]), "=r"(r[3]) : "r"(saddr));
}
__device__ __forceinline__ void cpa16(void* sp, const void* gp) {
    unsigned s = (unsigned)__cvta_generic_to_shared(sp);
    asm volatile("cp.async.cg.shared.global [%0], [%1], 16;" :: "r"(s), "l"(gp));
}

// ---------------- f32 -> fp16 conversions ----------------
__global__ void tohalf_plain(const float* __restrict__ s, __half* __restrict__ d) {
    const size_t i = ((size_t)blockIdx.x * 256 + threadIdx.x) * 4;
    float4 v = *(const float4*)(s + i);
    uint2 u;
    u.x = packh2(v.x, v.y);
    u.y = packh2(v.z, v.w);
    *(uint2*)((unsigned*)d + i / 2) = u;
}
__global__ void tohalf_pair(const float* __restrict__ W, unsigned* __restrict__ Wp, int N) {
    const int idx = blockIdx.x * 256 + threadIdx.x;
    const int nc4 = N / 4;
    const int kp = idx / nc4, c4 = (idx % nc4) * 4;
    const float4 w0 = *(const float4*)(W + (size_t)(2 * kp) * N + c4);
    const float4 w1 = *(const float4*)(W + (size_t)(2 * kp + 1) * N + c4);
    uint4 u;
    u.x = packh2(w0.x, w1.x);
    u.y = packh2(w0.y, w1.y);
    u.z = packh2(w0.z, w1.z);
    u.w = packh2(w0.w, w1.w);
    *(uint4*)(Wp + (size_t)kp * N + c4) = u;
}

// ---------------- fp16 tensor-core GEMM (ldmatrix A frags) ----------------
#define BM 128
#define BN 128
#define NK 64
#define PAH 20
#define PBH 136
#define STG_AH (128*PAH)
#define STG_BH (16*PBH)
#define GEMM_SMEMH (3*(STG_AH+STG_BH)*4)

__device__ __forceinline__ void gemmh_issue(const __half* __restrict__ A,
        const unsigned* __restrict__ Bp, int N, int bm, int bn,
        unsigned* As, unsigned* Bs, int kt,
        int arow, int apair, int brow, int bcol) {
    unsigned* Ad = As + (kt % 3) * STG_AH;
    const unsigned* Ag = (const unsigned*)A + (size_t)(bm + arow) * 1024 + kt * 16 + apair;
    cpa16(Ad + arow * PAH + apair,     Ag);
    cpa16(Ad + arow * PAH + apair + 4, Ag + 4);
    unsigned* Bd = Bs + (kt % 3) * STG_BH;
    const unsigned* Bg = Bp + (size_t)(kt * 16 + brow) * N + bn + bcol;
    cpa16(Bd + brow * PBH + bcol,     Bg);
    cpa16(Bd + brow * PBH + bcol + 4, Bg + 4);
    asm volatile("cp.async.commit_group;");
}

__device__ __forceinline__ void gemmh_core(const __half* __restrict__ A,
        const unsigned* __restrict__ Bp, float* __restrict__ C,
        int N, int bm, int bn, unsigned* As, unsigned* Bs) {
    const int tid  = threadIdx.x;
    const int lane = tid & 31;
    const int warp = tid >> 5;
    const int ly = lane >> 2, lx = lane & 3;
    const int wm = (warp & 3) * 32;
    const int wn = (warp >> 2) * 64;
    const int arow = tid >> 1, apair = (tid & 1) * 8;
    const int brow = tid >> 4, bcol = (tid & 15) * 8;
    // ldmatrix lane geometry for A fragments
    const int lrow   = (lane & 7) + ((lane >> 3) & 1) * 8;
    const int lchunk = ((lane >> 4) & 1) * 4;
    const unsigned As_s = (unsigned)__cvta_generic_to_shared(As);

    float acc[2][8][4];
    #pragma unroll
    for (int mi = 0; mi < 2; mi++)
        #pragma unroll
        for (int ni = 0; ni < 8; ni++)
            #pragma unroll
            for (int r = 0; r < 4; r++) acc[mi][ni][r] = 0.f;

    gemmh_issue(A, Bp, N, bm, bn, As, Bs, 0, arow, apair, brow, bcol);
    gemmh_issue(A, Bp, N, bm, bn, As, Bs, 1, arow, apair, brow, bcol);

    for (int kt = 0; kt < NK; kt++) {
        asm volatile("cp.async.wait_group 1;");
        __syncthreads();

        const unsigned AbS = As_s + (((kt % 3) * STG_AH) << 2);
        const unsigned* Bb = Bs + (kt % 3) * STG_BH;
        #pragma unroll
        for (int ks2 = 0; ks2 < 2; ks2++) {
            const int kp0 = ks2 * 8;
            unsigned af[2][4], bf[8][2];
            #pragma unroll
            for (int mi = 0; mi < 2; mi++)
                ldsm_x4(af[mi], AbS + (((wm + mi * 16 + lrow) * PAH + kp0 + lchunk) << 2));
            #pragma unroll
            for (int ni = 0; ni < 8; ni++) {
                const int n = wn + ni * 8 + ly;
                bf[ni][0] = Bb[(kp0 + lx) * PBH + n];
                bf[ni][1] = Bb[(kp0 + 4 + lx) * PBH + n];
            }
            #pragma unroll
            for (int mi = 0; mi < 2; mi++)
                #pragma unroll
                for (int ni = 0; ni < 8; ni++)
                    mma_f16(acc[mi][ni], af[mi], bf[ni]);
        }
        __syncthreads();

        if (kt + 2 < NK)
            gemmh_issue(A, Bp, N, bm, bn, As, Bs, kt + 2, arow, apair, brow, bcol);
        else
            asm volatile("cp.async.commit_group;");
    }

    #pragma unroll
    for (int mi = 0; mi < 2; mi++) {
        const int r0 = bm + wm + mi * 16 + ly;
        #pragma unroll
        for (int ni = 0; ni < 8; ni++) {
            const int c0 = bn + wn + ni * 8 + 2 * lx;
            *(float2*)(C + (size_t)r0 * N + c0)       = make_float2(acc[mi][ni][0], acc[mi][ni][1]);
            *(float2*)(C + (size_t)(r0 + 8) * N + c0) = make_float2(acc[mi][ni][2], acc[mi][ni][3]);
        }
    }
}

__global__ void __launch_bounds__(256, 2) gemm_qkv(const __half* __restrict__ A) {
    extern __shared__ unsigned smu[];
    const int bx = blockIdx.x;
    const unsigned* Bp; float* Cm; int N, bn;
    if (bx < 16)      { Bp = g_wqp; Cm = g_q; N = 2048; bn = bx * 128; }
    else if (bx < 20) { Bp = g_wkp; Cm = g_k; N = 512;  bn = (bx - 16) * 128; }
    else              { Bp = g_wvp; Cm = g_v; N = 512;  bn = (bx - 20) * 128; }
    gemmh_core(A, Bp, Cm, N, blockIdx.y * BM, bn, smu, smu + 3 * STG_AH);
}

__global__ void __launch_bounds__(256, 2) gemm_wo(const __half* __restrict__ A,
        float* __restrict__ C) {
    extern __shared__ unsigned smu[];
    gemmh_core(A, g_wop, C, HID_, blockIdx.y * BM, blockIdx.x * BN, smu, smu + 3 * STG_AH);
}

// ---------------- gate projection (exact fp32) ----------------
__global__ void gate_proj(const float* __restrict__ hs, const float* __restrict__ Wg) {
    const int s = blockIdx.x;
    const int w = threadIdx.x >> 5, l = threadIdx.x & 31;
    const float* row = hs + (size_t)s * HID_;
    float acc = 0.f;
    for (int k = l; k < HID_; k += 32)
        acc = fmaf(row[k], Wg[k * HKV_ + w], acc);
    #pragma unroll
    for (int o = 16; o > 0; o >>= 1)
        acc += __shfl_down_sync(0xffffffffu, acc, o);
    if (l == 0) g_g[s * HKV_ + w] = acc;
}

// ---------------- log-sigmoid + parallel cumsum ----------------
__global__ void gcumsum_kernel() {
    __shared__ float ps[256];
    const int kv = blockIdx.x;
    const int t = threadIdx.x;
    float loc[8]; float s = 0.f;
    #pragma unroll
    for (int i = 0; i < 8; i++) {
        const float x = g_g[(t * 8 + i) * HKV_ + kv];
        const float ls = (x > 0.f) ? -log1pf(__expf(-x)) : x - log1pf(__expf(x));
        loc[i] = ls; s += ls;
    }
    ps[t] = s; __syncthreads();
    for (int o = 1; o < 256; o <<= 1) {
        const float v = (t >= o) ? ps[t - o] : 0.f;
        __syncthreads();
        ps[t] += v;
        __syncthreads();
    }
    float run = (t > 0) ? ps[t - 1] : 0.f;
    #pragma unroll
    for (int i = 0; i < 8; i++) {
        run += loc[i];
        g_gc[kv * S_ + t * 8 + i] = run;
    }
}

// ---------------- fp16-split tensor-core power attention (ldmatrix) --------
#define PQ2 68     // Q/K pitch in u32 k-pairs (%32==4; 17r mod 8 bijective)
#define PS2 36     // S pitch in u32 j-pairs  (9r mod 8 bijective)
#define PV2 136    // V pitch in u32 (n index)
#define ATTN_SMEM ((4*64*PQ2 + 2*32*PV2 + 192) * 4)   // 105216 B

__global__ void __launch_bounds__(256, 2) attn_kernel(
        const float* __restrict__ cosb, const float* __restrict__ sinb) {
    extern __shared__ unsigned smu[];
    unsigned* Qhi = smu;                    // [64][PQ2]
    unsigned* Qlo = Qhi + 64 * PQ2;
    unsigned* Khi = Qlo + 64 * PQ2;         // [64][PQ2]; S aliases after QK
    unsigned* Klo = Khi + 64 * PQ2;
    unsigned* Vhi = Klo + 64 * PQ2;         // [32][PV2]
    unsigned* Vlo = Vhi + 32 * PV2;
    float* Gq  = (float*)(Vlo + 32 * PV2);
    float* Gk  = Gq + 64;
    float* den = Gk + 64;
    unsigned* Shi = Khi;                    // [64][PS2] alias
    unsigned* Slo = Klo;

    const unsigned Qhi_s = (unsigned)__cvta_generic_to_shared(Qhi);
    const unsigned Qlo_s = Qhi_s + 64 * PQ2 * 4;
    const unsigned Khi_s = Qlo_s + 64 * PQ2 * 4;
    const unsigned Klo_s = Khi_s + 64 * PQ2 * 4;
    const unsigned Shi_s = Khi_s;
    const unsigned Slo_s = Klo_s;

    const int qb = gridDim.x - 1 - blockIdx.x;
    const int h = blockIdx.y, kv = h / GROUPS_;
    const int tid  = threadIdx.x;
    const int lane = tid & 31, warp = tid >> 5;
    const int ly = lane >> 2, lx = lane & 3;
    const int wm  = (warp & 3) * 16;
    const int wn  = (warp >> 2) * 32;
    const int wn2 = (warp >> 2) * 64;
    // ldmatrix lane geometry
    const int lrow   = (lane & 7) + ((lane >> 3) & 1) * 8;    // A frags
    const int lchunk = ((lane >> 4) & 1) * 4;
    const int krow   = (lane & 7) + ((lane >> 4) & 1) * 8;    // K (B) frags
    const int kchunk = ((lane >> 3) & 1) * 4;

    // ---- load Q tile with fused rope + fp16 split ----
    #pragma unroll
    for (int j = 0; j < 8; j++) {
        const int idx = j * 256 + tid;
        const int r = idx >> 5, d0 = (idx & 31) * 4;
        const int srow = qb * 64 + r;
        const float* base = g_q + (size_t)srow * (H_ * D_) + h * D_;
        const float4 x  = *(const float4*)(base + d0);
        const float4 y  = *(const float4*)(base + (d0 ^ 64));
        const float4 c4 = *(const float4*)(cosb + srow * 128 + d0);
        const float4 s4 = *(const float4*)(sinb + srow * 128 + d0);
        const float sg = (d0 < 64) ? -1.f : 1.f;
        const float r0 = x.x * c4.x + sg * y.x * s4.x;
        const float r1 = x.y * c4.y + sg * y.y * s4.y;
        const float r2 = x.z * c4.z + sg * y.z * s4.z;
        const float r3 = x.w * c4.w + sg * y.w * s4.w;
        unsigned l0, l1;
        const unsigned h0 = sp_hi(r0, r1, l0);
        const unsigned h1 = sp_hi(r2, r3, l1);
        Qhi[r * PQ2 + d0 / 2]     = h0;
        Qhi[r * PQ2 + d0 / 2 + 1] = h1;
        Qlo[r * PQ2 + d0 / 2]     = l0;
        Qlo[r * PQ2 + d0 / 2 + 1] = l1;
    }
    if (tid < 64) { Gq[tid] = g_gc[kv * S_ + qb * 64 + tid]; den[tid] = 0.f; }
    __syncthreads();

    const float gq0 = Gq[wm + ly];
    const float gq1 = Gq[wm + ly + 8];
    const float Gq0 = Gq[0];

    float o[8][4];
    #pragma unroll
    for (int ni = 0; ni < 8; ni++)
        #pragma unroll
        for (int r = 0; r < 4; r++) o[ni][r] = 0.f;
    float rs0 = 0.f, rs1 = 0.f;

    for (int kb = qb; kb >= 0; kb--) {
        if (kb < qb && Gq0 - g_gc[kv * S_ + kb * 64 + 63] < DECAY_CUT) break;
        __syncthreads();   // prev SV done reading S/V

        // ---- K tile: rope + split ----
        #pragma unroll
        for (int j = 0; j < 8; j++) {
            const int idx = j * 256 + tid;
            const int r = idx >> 5, d0 = (idx & 31) * 4;
            const int srow = kb * 64 + r;
            const float* base = g_k + (size_t)srow * (HKV_ * D_) + kv * D_;
            const float4 x  = *(const float4*)(base + d0);
            const float4 y  = *(const float4*)(base + (d0 ^ 64));
            const float4 c4 = *(const float4*)(cosb + srow * 128 + d0);
            const float4 s4 = *(const float4*)(sinb + srow * 128 + d0);
            const float sg = (d0 < 64) ? -1.f : 1.f;
            const float r0 = x.x * c4.x + sg * y.x * s4.x;
            const float r1 = x.y * c4.y + sg * y.y * s4.y;
            const float r2 = x.z * c4.z + sg * y.z * s4.z;
            const float r3 = x.w * c4.w + sg * y.w * s4.w;
            unsigned l0, l1;
            const unsigned h0 = sp_hi(r0, r1, l0);
            const unsigned h1 = sp_hi(r2, r3, l1);
            Khi[r * PQ2 + d0 / 2]     = h0;
            Khi[r * PQ2 + d0 / 2 + 1] = h1;
            Klo[r * PQ2 + d0 / 2]     = l0;
            Klo[r * PQ2 + d0 / 2 + 1] = l1;
        }
        // ---- V tile: pack k-pairs across rows + split ----
        #pragma unroll
        for (int j = 0; j < 4; j++) {
            const int idx = j * 256 + tid;
            const int kp = idx >> 5, n0 = (idx & 31) * 4;
            const size_t b0 = (size_t)(kb * 64 + 2 * kp) * (HKV_ * D_) + kv * D_ + n0;
            const float4 v0 = *(const float4*)(g_v + b0);
            const float4 v1 = *(const float4*)(g_v + b0 + HKV_ * D_);
            unsigned l0, l1, l2, l3;
            Vhi[kp * PV2 + n0 + 0] = sp_hi(v0.x, v1.x, l0);
            Vhi[kp * PV2 + n0 + 1] = sp_hi(v0.y, v1.y, l1);
            Vhi[kp * PV2 + n0 + 2] = sp_hi(v0.z, v1.z, l2);
            Vhi[kp * PV2 + n0 + 3] = sp_hi(v0.w, v1.w, l3);
            Vlo[kp * PV2 + n0 + 0] = l0;
            Vlo[kp * PV2 + n0 + 1] = l1;
            Vlo[kp * PV2 + n0 + 2] = l2;
            Vlo[kp * PV2 + n0 + 3] = l3;
        }
        if (tid < 64) Gk[tid] = g_gc[kv * S_ + kb * 64 + tid];
        __syncthreads();

        // ---- S = QK^T (3x fp16-split mma, ldmatrix frags) ----
        float c[4][4];
        #pragma unroll
        for (int ni = 0; ni < 4; ni++)
            #pragma unroll
            for (int r = 0; r < 4; r++) c[ni][r] = 0.f;
        #pragma unroll
        for (int ks2 = 0; ks2 < 8; ks2++) {
            const int kp0 = ks2 * 8;
            unsigned ah[4], al[4];
            const unsigned qoff = (((wm + lrow) * PQ2 + kp0 + lchunk) << 2);
            ldsm_x4(ah, Qhi_s + qoff);
            ldsm_x4(al, Qlo_s + qoff);
            #pragma unroll
            for (int nb = 0; nb < 2; nb++) {
                const unsigned koff = (((wn + nb * 16 + krow) * PQ2 + kp0 + kchunk) << 2);
                unsigned bh4[4], bl4[4];
                ldsm_x4(bh4, Khi_s + koff);
                ldsm_x4(bl4, Klo_s + koff);
                mma_f16(c[2 * nb],     ah, &bh4[0]);
                mma_f16(c[2 * nb],     al, &bh4[0]);
                mma_f16(c[2 * nb],     ah, &bl4[0]);
                mma_f16(c[2 * nb + 1], ah, &bh4[2]);
                mma_f16(c[2 * nb + 1], al, &bh4[2]);
                mma_f16(c[2 * nb + 1], ah, &bl4[2]);
            }
        }
        float gk0v[4], gk1v[4];
        #pragma unroll
        for (int ni = 0; ni < 4; ni++) {
            const int col = wn + ni * 8 + 2 * lx;
            gk0v[ni] = Gk[col];
            gk1v[ni] = Gk[col + 1];
        }
        __syncthreads();   // all warps done reading K -> S may overwrite

        // ---- mask, scale^2, decay; rowsums; stage S (x512, split) ----
        const int rg0 = qb * 64 + wm + ly;
        const int rg1 = rg0 + 8;
        #pragma unroll
        for (int ni = 0; ni < 4; ni++) {
            const int col = wn + ni * 8 + 2 * lx;
            const int cg  = kb * 64 + col;
            float t;
            t = c[ni][0] * SCALE_;
            const float v00 = (cg     <= rg0) ? t * t * __expf(gq0 - gk0v[ni]) : 0.f;
            t = c[ni][1] * SCALE_;
            const float v01 = (cg + 1 <= rg0) ? t * t * __expf(gq0 - gk1v[ni]) : 0.f;
            t = c[ni][2] * SCALE_;
            const float v10 = (cg     <= rg1) ? t * t * __expf(gq1 - gk0v[ni]) : 0.f;
            t = c[ni][3] * SCALE_;
            const float v11 = (cg + 1 <= rg1) ? t * t * __expf(gq1 - gk1v[ni]) : 0.f;
            rs0 += v00 + v01;
            rs1 += v10 + v11;
            const int sp = wn / 2 + 4 * ni + lx;
            unsigned l0, l1;
            Shi[(wm + ly) * PS2 + sp]     = sp_hi(v00 * SSCALE, v01 * SSCALE, l0);
            Shi[(wm + ly + 8) * PS2 + sp] = sp_hi(v10 * SSCALE, v11 * SSCALE, l1);
            Slo[(wm + ly) * PS2 + sp]     = l0;
            Slo[(wm + ly + 8) * PS2 + sp] = l1;
        }
        __syncthreads();

        // ---- O += S @ V (3x fp16-split mma, ldmatrix S frags) ----
        #pragma unroll
        for (int ks2 = 0; ks2 < 4; ks2++) {
            const int jp0 = ks2 * 8;
            unsigned ah[4], al[4];
            const unsigned soff = (((wm + lrow) * PS2 + jp0 + lchunk) << 2);
            ldsm_x4(ah, Shi_s + soff);
            ldsm_x4(al, Slo_s + soff);
            #pragma unroll
            for (int ni = 0; ni < 8; ni++) {
                const int n = wn2 + ni * 8 + ly;
                unsigned bh[2], bl[2];
                bh[0] = Vhi[(jp0 + lx) * PV2 + n];
                bh[1] = Vhi[(jp0 + 4 + lx) * PV2 + n];
                bl[0] = Vlo[(jp0 + lx) * PV2 + n];
                bl[1] = Vlo[(jp0 + 4 + lx) * PV2 + n];
                mma_f16(o[ni], ah, bh);
                mma_f16(o[ni], al, bh);
                mma_f16(o[ni], ah, bl);
            }
        }
    }

    rs0 += __shfl_xor_sync(0xffffffffu, rs0, 1);
    rs0 += __shfl_xor_sync(0xffffffffu, rs0, 2);
    rs1 += __shfl_xor_sync(0xffffffffu, rs1, 1);
    rs1 += __shfl_xor_sync(0xffffffffu, rs1, 2);
    if (lx == 0) {
        atomicAdd(&den[wm + ly], rs0);
        atomicAdd(&den[wm + ly + 8], rs1);
    }
    __syncthreads();

    const float inv0 = INV_SSCALE / fmaxf(den[wm + ly], 1.f);
    const float inv1 = INV_SSCALE / fmaxf(den[wm + ly + 8], 1.f);
    unsigned* ah32 = (unsigned*)g_attnh;
    #pragma unroll
    for (int ni = 0; ni < 8; ni++) {
        const int colg = h * D_ + wn2 + ni * 8 + 2 * lx;
        const size_t i0 = ((size_t)(qb * 64 + wm + ly) * (H_ * D_) + colg) / 2;
        const size_t i1 = ((size_t)(qb * 64 + wm + ly + 8) * (H_ * D_) + colg) / 2;
        ah32[i0] = packh2(o[ni][0] * inv0, o[ni][1] * inv0);
        ah32[i1] = packh2(o[ni][2] * inv1, o[ni][3] * inv1);
    }
}

// ---------------- launch ----------------
extern "C" void kernel_launch(void* const* d_in, const int* in_sizes, int n_in,
                              void* d_out, int out_size) {
    (void)in_sizes; (void)n_in; (void)out_size;
    const float* hs   = (const float*)d_in[0];
    const float* cosb = (const float*)d_in[1];
    const float* sinb = (const float*)d_in[2];
    const float* Wq   = (const float*)d_in[3];
    const float* Wk   = (const float*)d_in[4];
    const float* Wv   = (const float*)d_in[5];
    const float* Wg   = (const float*)d_in[6];
    const float* Wo   = (const float*)d_in[7];
    float* out = (float*)d_out;

    __half *hsh, *attnh;
    unsigned *wqp, *wkp, *wvp, *wop;
    cudaGetSymbolAddress((void**)&hsh,   g_hsh);
    cudaGetSymbolAddress((void**)&attnh, g_attnh);
    cudaGetSymbolAddress((void**)&wqp,   g_wqp);
    cudaGetSymbolAddress((void**)&wkp,   g_wkp);
    cudaGetSymbolAddress((void**)&wvp,   g_wvp);
    cudaGetSymbolAddress((void**)&wop,   g_wop);

    static cudaStream_t s1 = nullptr, s2 = nullptr, s3 = nullptr;
    static cudaEvent_t ev0, ev1, ev2, ev2a, ev3;
    if (!s1) {
        cudaStreamCreateWithFlags(&s1, cudaStreamNonBlocking);
        cudaStreamCreateWithFlags(&s2, cudaStreamNonBlocking);
        cudaStreamCreateWithFlags(&s3, cudaStreamNonBlocking);
        cudaEventCreateWithFlags(&ev0,  cudaEventDisableTiming);
        cudaEventCreateWithFlags(&ev1,  cudaEventDisableTiming);
        cudaEventCreateWithFlags(&ev2,  cudaEventDisableTiming);
        cudaEventCreateWithFlags(&ev2a, cudaEventDisableTiming);
        cudaEventCreateWithFlags(&ev3,  cudaEventDisableTiming);
    }

    cudaFuncSetAttribute(gemm_qkv, cudaFuncAttributeMaxDynamicSharedMemorySize, GEMM_SMEMH);
    cudaFuncSetAttribute(gemm_wo,  cudaFuncAttributeMaxDynamicSharedMemorySize, GEMM_SMEMH);
    cudaFuncSetAttribute(attn_kernel, cudaFuncAttributeMaxDynamicSharedMemorySize, ATTN_SMEM);

    cudaEventRecord(ev0, 0);

    // side stream 2: Wq pair-pack
    cudaStreamWaitEvent(s2, ev0, 0);
    tohalf_pair<<<(HID_/2)*(H_*D_)/4/256, 256, 0, s2>>>(Wq, wqp, H_*D_);
    cudaEventRecord(ev2a, s2);

    // side stream 3: Wk, Wv, then Wo pair-packs
    cudaStreamWaitEvent(s3, ev0, 0);
    tohalf_pair<<<(HID_/2)*(HKV_*D_)/4/256, 256, 0, s3>>>(Wk, wkp, HKV_*D_);
    tohalf_pair<<<(HID_/2)*(HKV_*D_)/4/256, 256, 0, s3>>>(Wv, wvp, HKV_*D_);
    cudaEventRecord(ev3, s3);
    tohalf_pair<<<((H_*D_)/2)*HID_/4/256, 256, 0, s3>>>(Wo, wop, HID_);
    cudaEventRecord(ev2, s3);

    // side stream 1: gate path (exact fp32)
    cudaStreamWaitEvent(s1, ev0, 0);
    gate_proj<<<S_, 128, 0, s1>>>(hs, Wg);
    gcumsum_kernel<<<HKV_, 256, 0, s1>>>();
    cudaEventRecord(ev1, s1);

    // main stream
    tohalf_plain<<<(S_*HID_) / 1024, 256>>>(hs, hsh);
    cudaStreamWaitEvent(0, ev2a, 0);
    cudaStreamWaitEvent(0, ev3, 0);
    gemm_qkv<<<dim3(24, S_ / BM), 256, GEMM_SMEMH>>>(hsh);

    cudaStreamWaitEvent(0, ev1, 0);
    attn_kernel<<<dim3(S_ / 64, H_), 256, ATTN_SMEM>>>(cosb, sinb);

    cudaStreamWaitEvent(0, ev2, 0);
    gemm_wo<<<dim3(HID_ / BN, S_ / BM), 256, GEMM_SMEMH>>>(attnh, out);
}

// round 14
// speedup vs baseline: 1.8075x; 1.0031x over previous
#include <cuda_runtime.h>
#include <cuda_fp16.h>
#include <math.h>

#define S_     2048
#define HID_   2048
#define H_     16
#define HKV_   4
#define D_     128
#define GROUPS_ 4
#define SCALE_ 0.08838834764831845f   // 128^-0.5
#define DECAY_CUT (-25.0f)
#define SSCALE 512.0f
#define INV_SSCALE (1.0f/512.0f)

// ---------------- scratch (no cudaMalloc allowed) ----------------
__device__ float    g_q    [S_*H_*D_];          // unroped; rope applied in attn loader
__device__ float    g_k    [S_*HKV_*D_];
__device__ float    g_v    [S_*HKV_*D_];
__device__ float    g_g    [S_*HKV_];
__device__ float    g_gc   [HKV_*S_];
__device__ __half   g_attnh[S_*H_*D_];
__device__ __half   g_hsh  [S_*HID_];
__device__ unsigned g_wqp  [(HID_/2)*(H_*D_)];
__device__ unsigned g_wkp  [(HID_/2)*(HKV_*D_)];
__device__ unsigned g_wvp  [(HID_/2)*(HKV_*D_)];
__device__ unsigned g_wop  [((H_*D_)/2)*HID_];

// ---------------- helpers ----------------
__device__ __forceinline__ unsigned packh2(float lo, float hi) {
    __half2 h = __floats2half2_rn(lo, hi);
    return *(unsigned*)&h;
}
__device__ __forceinline__ unsigned sp_hi(float a, float b, unsigned& lo) {
    const __half ha = __float2half_rn(a), hb = __float2half_rn(b);
    lo = packh2(a - __half2float(ha), b - __half2float(hb));
    const __half2 hh = __halves2half2(ha, hb);
    return *(unsigned*)&hh;
}
__device__ __forceinline__ void mma_f16(float c[4], const unsigned a[4], const unsigned b[2]) {
    asm volatile("mma.sync.aligned.m16n8k16.row.col.f32.f16.f16.f32 "
        "{%0,%1,%2,%3},{%4,%5,%6,%7},{%8,%9},{%0,%1,%2,%3};"
        : "+f"(c[0]), "+f"(c[1]), "+f"(c[2]), "+f"(c[3])
        : "r"(a[0]), "r"(a[1]), "r"(a[2]), "r"(a[3]), "r"(b[0]), "r"(b[1]));
}
__device__ __forceinline__ void ldsm_x4(unsigned r[4], unsigned saddr) {
    asm volatile("ldmatrix.sync.aligned.m8n8.x4.shared.b16 {%0,%1,%2,%3}, [%4];"
        : "=r"(r[0]), "=r"(r[1]), "=r"(r[2]), "=r"(r[3]) : "r"(saddr));
}
__device__ __forceinline__ void cpa16(void* sp, const void* gp) {
    unsigned s = (unsigned)__cvta_generic_to_shared(sp);
    asm volatile("cp.async.cg.shared.global [%0], [%1], 16;" :: "r"(s), "l"(gp));
}

// ---------------- f32 -> fp16 conversions ----------------
__global__ void tohalf_plain(const float* __restrict__ s, __half* __restrict__ d) {
    const size_t i = ((size_t)blockIdx.x * 256 + threadIdx.x) * 4;
    float4 v = *(const float4*)(s + i);
    uint2 u;
    u.x = packh2(v.x, v.y);
    u.y = packh2(v.z, v.w);
    *(uint2*)((unsigned*)d + i / 2) = u;
}
__global__ void tohalf_pair(const float* __restrict__ W, unsigned* __restrict__ Wp, int N) {
    const int idx = blockIdx.x * 256 + threadIdx.x;
    const int nc4 = N / 4;
    const int kp = idx / nc4, c4 = (idx % nc4) * 4;
    const float4 w0 = *(const float4*)(W + (size_t)(2 * kp) * N + c4);
    const float4 w1 = *(const float4*)(W + (size_t)(2 * kp + 1) * N + c4);
    uint4 u;
    u.x = packh2(w0.x, w1.x);
    u.y = packh2(w0.y, w1.y);
    u.z = packh2(w0.z, w1.z);
    u.w = packh2(w0.w, w1.w);
    *(uint4*)(Wp + (size_t)kp * N + c4) = u;
}

// ---------------- fp16 tensor-core GEMM (R11, proven) ----------------
#define BM 128
#define BN 128
#define NK 64
#define PAH 20
#define PBH 136
#define STG_AH (128*PAH)
#define STG_BH (16*PBH)
#define GEMM_SMEMH (3*(STG_AH+STG_BH)*4)

__device__ __forceinline__ void gemmh_issue(const __half* __restrict__ A,
        const unsigned* __restrict__ Bp, int N, int bm, int bn,
        unsigned* As, unsigned* Bs, int kt,
        int arow, int apair, int brow, int bcol) {
    unsigned* Ad = As + (kt % 3) * STG_AH;
    const unsigned* Ag = (const unsigned*)A + (size_t)(bm + arow) * 1024 + kt * 16 + apair;
    cpa16(Ad + arow * PAH + apair,     Ag);
    cpa16(Ad + arow * PAH + apair + 4, Ag + 4);
    unsigned* Bd = Bs + (kt % 3) * STG_BH;
    const unsigned* Bg = Bp + (size_t)(kt * 16 + brow) * N + bn + bcol;
    cpa16(Bd + brow * PBH + bcol,     Bg);
    cpa16(Bd + brow * PBH + bcol + 4, Bg + 4);
    asm volatile("cp.async.commit_group;");
}

__device__ __forceinline__ void gemmh_core(const __half* __restrict__ A,
        const unsigned* __restrict__ Bp, float* __restrict__ C,
        int N, int bm, int bn, unsigned* As, unsigned* Bs) {
    const int tid  = threadIdx.x;
    const int lane = tid & 31;
    const int warp = tid >> 5;
    const int ly = lane >> 2, lx = lane & 3;
    const int wm = (warp & 3) * 32;
    const int wn = (warp >> 2) * 64;
    const int arow = tid >> 1, apair = (tid & 1) * 8;
    const int brow = tid >> 4, bcol = (tid & 15) * 8;
    const int lrow   = (lane & 7) + ((lane >> 3) & 1) * 8;
    const int lchunk = ((lane >> 4) & 1) * 4;
    const unsigned As_s = (unsigned)__cvta_generic_to_shared(As);

    float acc[2][8][4];
    #pragma unroll
    for (int mi = 0; mi < 2; mi++)
        #pragma unroll
        for (int ni = 0; ni < 8; ni++)
            #pragma unroll
            for (int r = 0; r < 4; r++) acc[mi][ni][r] = 0.f;

    gemmh_issue(A, Bp, N, bm, bn, As, Bs, 0, arow, apair, brow, bcol);
    gemmh_issue(A, Bp, N, bm, bn, As, Bs, 1, arow, apair, brow, bcol);

    for (int kt = 0; kt < NK; kt++) {
        asm volatile("cp.async.wait_group 1;");
        __syncthreads();

        const unsigned AbS = As_s + (((kt % 3) * STG_AH) << 2);
        const unsigned* Bb = Bs + (kt % 3) * STG_BH;
        #pragma unroll
        for (int ks2 = 0; ks2 < 2; ks2++) {
            const int kp0 = ks2 * 8;
            unsigned af[2][4], bf[8][2];
            #pragma unroll
            for (int mi = 0; mi < 2; mi++)
                ldsm_x4(af[mi], AbS + (((wm + mi * 16 + lrow) * PAH + kp0 + lchunk) << 2));
            #pragma unroll
            for (int ni = 0; ni < 8; ni++) {
                const int n = wn + ni * 8 + ly;
                bf[ni][0] = Bb[(kp0 + lx) * PBH + n];
                bf[ni][1] = Bb[(kp0 + 4 + lx) * PBH + n];
            }
            #pragma unroll
            for (int mi = 0; mi < 2; mi++)
                #pragma unroll
                for (int ni = 0; ni < 8; ni++)
                    mma_f16(acc[mi][ni], af[mi], bf[ni]);
        }
        __syncthreads();

        if (kt + 2 < NK)
            gemmh_issue(A, Bp, N, bm, bn, As, Bs, kt + 2, arow, apair, brow, bcol);
        else
            asm volatile("cp.async.commit_group;");
    }

    #pragma unroll
    for (int mi = 0; mi < 2; mi++) {
        const int r0 = bm + wm + mi * 16 + ly;
        #pragma unroll
        for (int ni = 0; ni < 8; ni++) {
            const int c0 = bn + wn + ni * 8 + 2 * lx;
            *(float2*)(C + (size_t)r0 * N + c0)       = make_float2(acc[mi][ni][0], acc[mi][ni][1]);
            *(float2*)(C + (size_t)(r0 + 8) * N + c0) = make_float2(acc[mi][ni][2], acc[mi][ni][3]);
        }
    }
}

__global__ void __launch_bounds__(256, 2) gemm_qkv(const __half* __restrict__ A) {
    extern __shared__ unsigned smu[];
    const int bx = blockIdx.x;
    const unsigned* Bp; float* Cm; int N, bn;
    if (bx < 16)      { Bp = g_wqp; Cm = g_q; N = 2048; bn = bx * 128; }
    else if (bx < 20) { Bp = g_wkp; Cm = g_k; N = 512;  bn = (bx - 16) * 128; }
    else              { Bp = g_wvp; Cm = g_v; N = 512;  bn = (bx - 20) * 128; }
    gemmh_core(A, Bp, Cm, N, blockIdx.y * BM, bn, smu, smu + 3 * STG_AH);
}

__global__ void __launch_bounds__(256, 2) gemm_wo(const __half* __restrict__ A,
        float* __restrict__ C) {
    extern __shared__ unsigned smu[];
    gemmh_core(A, g_wop, C, HID_, blockIdx.y * BM, blockIdx.x * BN, smu, smu + 3 * STG_AH);
}

// ---------------- gate projection (exact fp32) ----------------
__global__ void gate_proj(const float* __restrict__ hs, const float* __restrict__ Wg) {
    const int s = blockIdx.x;
    const int w = threadIdx.x >> 5, l = threadIdx.x & 31;
    const float* row = hs + (size_t)s * HID_;
    float acc = 0.f;
    for (int k = l; k < HID_; k += 32)
        acc = fmaf(row[k], Wg[k * HKV_ + w], acc);
    #pragma unroll
    for (int o = 16; o > 0; o >>= 1)
        acc += __shfl_down_sync(0xffffffffu, acc, o);
    if (l == 0) g_g[s * HKV_ + w] = acc;
}

// ---------------- log-sigmoid + parallel cumsum ----------------
__global__ void gcumsum_kernel() {
    __shared__ float ps[256];
    const int kv = blockIdx.x;
    const int t = threadIdx.x;
    float loc[8]; float s = 0.f;
    #pragma unroll
    for (int i = 0; i < 8; i++) {
        const float x = g_g[(t * 8 + i) * HKV_ + kv];
        const float ls = (x > 0.f) ? -log1pf(__expf(-x)) : x - log1pf(__expf(x));
        loc[i] = ls; s += ls;
    }
    ps[t] = s; __syncthreads();
    for (int o = 1; o < 256; o <<= 1) {
        const float v = (t >= o) ? ps[t - o] : 0.f;
        __syncthreads();
        ps[t] += v;
        __syncthreads();
    }
    float run = (t > 0) ? ps[t - 1] : 0.f;
    #pragma unroll
    for (int i = 0; i < 8; i++) {
        run += loc[i];
        g_gc[kv * S_ + t * 8 + i] = run;
    }
}

// ---------------- fp16-split tensor-core power attention (R11) -----------
#define PQ2 68
#define PS2 36
#define PV2 136
#define ATTN_SMEM ((4*64*PQ2 + 2*32*PV2 + 192) * 4)   // 105216 B

__global__ void __launch_bounds__(256, 2) attn_kernel(
        const float* __restrict__ cosb, const float* __restrict__ sinb) {
    extern __shared__ unsigned smu[];
    unsigned* Qhi = smu;
    unsigned* Qlo = Qhi + 64 * PQ2;
    unsigned* Khi = Qlo + 64 * PQ2;
    unsigned* Klo = Khi + 64 * PQ2;
    unsigned* Vhi = Klo + 64 * PQ2;
    unsigned* Vlo = Vhi + 32 * PV2;
    float* Gq  = (float*)(Vlo + 32 * PV2);
    float* Gk  = Gq + 64;
    float* den = Gk + 64;
    unsigned* Shi = Khi;
    unsigned* Slo = Klo;

    const unsigned Qhi_s = (unsigned)__cvta_generic_to_shared(Qhi);
    const unsigned Qlo_s = Qhi_s + 64 * PQ2 * 4;
    const unsigned Khi_s = Qlo_s + 64 * PQ2 * 4;
    const unsigned Klo_s = Khi_s + 64 * PQ2 * 4;
    const unsigned Shi_s = Khi_s;
    const unsigned Slo_s = Klo_s;

    const int qb = gridDim.x - 1 - blockIdx.x;
    const int h = blockIdx.y, kv = h / GROUPS_;
    const int tid  = threadIdx.x;
    const int lane = tid & 31, warp = tid >> 5;
    const int ly = lane >> 2, lx = lane & 3;
    const int wm  = (warp & 3) * 16;
    const int wn  = (warp >> 2) * 32;
    const int wn2 = (warp >> 2) * 64;
    const int lrow   = (lane & 7) + ((lane >> 3) & 1) * 8;
    const int lchunk = ((lane >> 4) & 1) * 4;
    const int krow   = (lane & 7) + ((lane >> 4) & 1) * 8;
    const int kchunk = ((lane >> 3) & 1) * 4;

    #pragma unroll
    for (int j = 0; j < 8; j++) {
        const int idx = j * 256 + tid;
        const int r = idx >> 5, d0 = (idx & 31) * 4;
        const int srow = qb * 64 + r;
        const float* base = g_q + (size_t)srow * (H_ * D_) + h * D_;
        const float4 x  = *(const float4*)(base + d0);
        const float4 y  = *(const float4*)(base + (d0 ^ 64));
        const float4 c4 = *(const float4*)(cosb + srow * 128 + d0);
        const float4 s4 = *(const float4*)(sinb + srow * 128 + d0);
        const float sg = (d0 < 64) ? -1.f : 1.f;
        const float r0 = x.x * c4.x + sg * y.x * s4.x;
        const float r1 = x.y * c4.y + sg * y.y * s4.y;
        const float r2 = x.z * c4.z + sg * y.z * s4.z;
        const float r3 = x.w * c4.w + sg * y.w * s4.w;
        unsigned l0, l1;
        const unsigned h0 = sp_hi(r0, r1, l0);
        const unsigned h1 = sp_hi(r2, r3, l1);
        Qhi[r * PQ2 + d0 / 2]     = h0;
        Qhi[r * PQ2 + d0 / 2 + 1] = h1;
        Qlo[r * PQ2 + d0 / 2]     = l0;
        Qlo[r * PQ2 + d0 / 2 + 1] = l1;
    }
    if (tid < 64) { Gq[tid] = g_gc[kv * S_ + qb * 64 + tid]; den[tid] = 0.f; }
    __syncthreads();

    const float gq0 = Gq[wm + ly];
    const float gq1 = Gq[wm + ly + 8];
    const float Gq0 = Gq[0];

    float o[8][4];
    #pragma unroll
    for (int ni = 0; ni < 8; ni++)
        #pragma unroll
        for (int r = 0; r < 4; r++) o[ni][r] = 0.f;
    float rs0 = 0.f, rs1 = 0.f;

    for (int kb = qb; kb >= 0; kb--) {
        if (kb < qb && Gq0 - g_gc[kv * S_ + kb * 64 + 63] < DECAY_CUT) break;
        __syncthreads();

        #pragma unroll
        for (int j = 0; j < 8; j++) {
            const int idx = j * 256 + tid;
            const int r = idx >> 5, d0 = (idx & 31) * 4;
            const int srow = kb * 64 + r;
            const float* base = g_k + (size_t)srow * (HKV_ * D_) + kv * D_;
            const float4 x  = *(const float4*)(base + d0);
            const float4 y  = *(const float4*)(base + (d0 ^ 64));
            const float4 c4 = *(const float4*)(cosb + srow * 128 + d0);
            const float4 s4 = *(const float4*)(sinb + srow * 128 + d0);
            const float sg = (d0 < 64) ? -1.f : 1.f;
            const float r0 = x.x * c4.x + sg * y.x * s4.x;
            const float r1 = x.y * c4.y + sg * y.y * s4.y;
            const float r2 = x.z * c4.z + sg * y.z * s4.z;
            const float r3 = x.w * c4.w + sg * y.w * s4.w;
            unsigned l0, l1;
            const unsigned h0 = sp_hi(r0, r1, l0);
            const unsigned h1 = sp_hi(r2, r3, l1);
            Khi[r * PQ2 + d0 / 2]     = h0;
            Khi[r * PQ2 + d0 / 2 + 1] = h1;
            Klo[r * PQ2 + d0 / 2]     = l0;
            Klo[r * PQ2 + d0 / 2 + 1] = l1;
        }
        #pragma unroll
        for (int j = 0; j < 4; j++) {
            const int idx = j * 256 + tid;
            const int kp = idx >> 5, n0 = (idx & 31) * 4;
            const size_t b0 = (size_t)(kb * 64 + 2 * kp) * (HKV_ * D_) + kv * D_ + n0;
            const float4 v0 = *(const float4*)(g_v + b0);
            const float4 v1 = *(const float4*)(g_v + b0 + HKV_ * D_);
            unsigned l0, l1, l2, l3;
            Vhi[kp * PV2 + n0 + 0] = sp_hi(v0.x, v1.x, l0);
            Vhi[kp * PV2 + n0 + 1] = sp_hi(v0.y, v1.y, l1);
            Vhi[kp * PV2 + n0 + 2] = sp_hi(v0.z, v1.z, l2);
            Vhi[kp * PV2 + n0 + 3] = sp_hi(v0.w, v1.w, l3);
            Vlo[kp * PV2 + n0 + 0] = l0;
            Vlo[kp * PV2 + n0 + 1] = l1;
            Vlo[kp * PV2 + n0 + 2] = l2;
            Vlo[kp * PV2 + n0 + 3] = l3;
        }
        if (tid < 64) Gk[tid] = g_gc[kv * S_ + kb * 64 + tid];
        __syncthreads();

        float c[4][4];
        #pragma unroll
        for (int ni = 0; ni < 4; ni++)
            #pragma unroll
            for (int r = 0; r < 4; r++) c[ni][r] = 0.f;
        #pragma unroll
        for (int ks2 = 0; ks2 < 8; ks2++) {
            const int kp0 = ks2 * 8;
            unsigned ah[4], al[4];
            const unsigned qoff = (((wm + lrow) * PQ2 + kp0 + lchunk) << 2);
            ldsm_x4(ah, Qhi_s + qoff);
            ldsm_x4(al, Qlo_s + qoff);
            #pragma unroll
            for (int nb = 0; nb < 2; nb++) {
                const unsigned koff = (((wn + nb * 16 + krow) * PQ2 + kp0 + kchunk) << 2);
                unsigned bh4[4], bl4[4];
                ldsm_x4(bh4, Khi_s + koff);
                ldsm_x4(bl4, Klo_s + koff);
                mma_f16(c[2 * nb],     ah, &bh4[0]);
                mma_f16(c[2 * nb],     al, &bh4[0]);
                mma_f16(c[2 * nb],     ah, &bl4[0]);
                mma_f16(c[2 * nb + 1], ah, &bh4[2]);
                mma_f16(c[2 * nb + 1], al, &bh4[2]);
                mma_f16(c[2 * nb + 1], ah, &bl4[2]);
            }
        }
        float gk0v[4], gk1v[4];
        #pragma unroll
        for (int ni = 0; ni < 4; ni++) {
            const int col = wn + ni * 8 + 2 * lx;
            gk0v[ni] = Gk[col];
            gk1v[ni] = Gk[col + 1];
        }
        __syncthreads();

        const int rg0 = qb * 64 + wm + ly;
        const int rg1 = rg0 + 8;
        #pragma unroll
        for (int ni = 0; ni < 4; ni++) {
            const int col = wn + ni * 8 + 2 * lx;
            const int cg  = kb * 64 + col;
            float t;
            t = c[ni][0] * SCALE_;
            const float v00 = (cg     <= rg0) ? t * t * __expf(gq0 - gk0v[ni]) : 0.f;
            t = c[ni][1] * SCALE_;
            const float v01 = (cg + 1 <= rg0) ? t * t * __expf(gq0 - gk1v[ni]) : 0.f;
            t = c[ni][2] * SCALE_;
            const float v10 = (cg     <= rg1) ? t * t * __expf(gq1 - gk0v[ni]) : 0.f;
            t = c[ni][3] * SCALE_;
            const float v11 = (cg + 1 <= rg1) ? t * t * __expf(gq1 - gk1v[ni]) : 0.f;
            rs0 += v00 + v01;
            rs1 += v10 + v11;
            const int sp = wn / 2 + 4 * ni + lx;
            unsigned l0, l1;
            Shi[(wm + ly) * PS2 + sp]     = sp_hi(v00 * SSCALE, v01 * SSCALE, l0);
            Shi[(wm + ly + 8) * PS2 + sp] = sp_hi(v10 * SSCALE, v11 * SSCALE, l1);
            Slo[(wm + ly) * PS2 + sp]     = l0;
            Slo[(wm + ly + 8) * PS2 + sp] = l1;
        }
        __syncthreads();

        #pragma unroll
        for (int ks2 = 0; ks2 < 4; ks2++) {
            const int jp0 = ks2 * 8;
            unsigned ah[4], al[4];
            const unsigned soff = (((wm + lrow) * PS2 + jp0 + lchunk) << 2);
            ldsm_x4(ah, Shi_s + soff);
            ldsm_x4(al, Slo_s + soff);
            #pragma unroll
            for (int ni = 0; ni < 8; ni++) {
                const int n = wn2 + ni * 8 + ly;
                unsigned bh[2], bl[2];
                bh[0] = Vhi[(jp0 + lx) * PV2 + n];
                bh[1] = Vhi[(jp0 + 4 + lx) * PV2 + n];
                bl[0] = Vlo[(jp0 + lx) * PV2 + n];
                bl[1] = Vlo[(jp0 + 4 + lx) * PV2 + n];
                mma_f16(o[ni], ah, bh);
                mma_f16(o[ni], al, bh);
                mma_f16(o[ni], ah, bl);
            }
        }
    }

    rs0 += __shfl_xor_sync(0xffffffffu, rs0, 1);
    rs0 += __shfl_xor_sync(0xffffffffu, rs0, 2);
    rs1 += __shfl_xor_sync(0xffffffffu, rs1, 1);
    rs1 += __shfl_xor_sync(0xffffffffu, rs1, 2);
    if (lx == 0) {
        atomicAdd(&den[wm + ly], rs0);
        atomicAdd(&den[wm + ly + 8], rs1);
    }
    __syncthreads();

    const float inv0 = INV_SSCALE / fmaxf(den[wm + ly], 1.f);
    const float inv1 = INV_SSCALE / fmaxf(den[wm + ly + 8], 1.f);
    unsigned* ah32 = (unsigned*)g_attnh;
    #pragma unroll
    for (int ni = 0; ni < 8; ni++) {
        const int colg = h * D_ + wn2 + ni * 8 + 2 * lx;
        const size_t i0 = ((size_t)(qb * 64 + wm + ly) * (H_ * D_) + colg) / 2;
        const size_t i1 = ((size_t)(qb * 64 + wm + ly + 8) * (H_ * D_) + colg) / 2;
        ah32[i0] = packh2(o[ni][0] * inv0, o[ni][1] * inv0);
        ah32[i1] = packh2(o[ni][2] * inv1, o[ni][3] * inv1);
    }
}

// ---------------- launch ----------------
extern "C" void kernel_launch(void* const* d_in, const int* in_sizes, int n_in,
                              void* d_out, int out_size) {
    (void)in_sizes; (void)n_in; (void)out_size;
    const float* hs   = (const float*)d_in[0];
    const float* cosb = (const float*)d_in[1];
    const float* sinb = (const float*)d_in[2];
    const float* Wq   = (const float*)d_in[3];
    const float* Wk   = (const float*)d_in[4];
    const float* Wv   = (const float*)d_in[5];
    const float* Wg   = (const float*)d_in[6];
    const float* Wo   = (const float*)d_in[7];
    float* out = (float*)d_out;

    __half *hsh, *attnh;
    unsigned *wqp, *wkp, *wvp, *wop;
    cudaGetSymbolAddress((void**)&hsh,   g_hsh);
    cudaGetSymbolAddress((void**)&attnh, g_attnh);
    cudaGetSymbolAddress((void**)&wqp,   g_wqp);
    cudaGetSymbolAddress((void**)&wkp,   g_wkp);
    cudaGetSymbolAddress((void**)&wvp,   g_wvp);
    cudaGetSymbolAddress((void**)&wop,   g_wop);

    static cudaStream_t s1 = nullptr, s2 = nullptr, s3 = nullptr;
    static cudaEvent_t ev0, ev1, ev2, ev2a, ev3;
    if (!s1) {
        cudaStreamCreateWithFlags(&s1, cudaStreamNonBlocking);
        cudaStreamCreateWithFlags(&s2, cudaStreamNonBlocking);
        cudaStreamCreateWithFlags(&s3, cudaStreamNonBlocking);
        cudaEventCreateWithFlags(&ev0,  cudaEventDisableTiming);
        cudaEventCreateWithFlags(&ev1,  cudaEventDisableTiming);
        cudaEventCreateWithFlags(&ev2,  cudaEventDisableTiming);
        cudaEventCreateWithFlags(&ev2a, cudaEventDisableTiming);
        cudaEventCreateWithFlags(&ev3,  cudaEventDisableTiming);
    }

    cudaFuncSetAttribute(gemm_qkv, cudaFuncAttributeMaxDynamicSharedMemorySize, GEMM_SMEMH);
    cudaFuncSetAttribute(gemm_wo,  cudaFuncAttributeMaxDynamicSharedMemorySize, GEMM_SMEMH);
    cudaFuncSetAttribute(attn_kernel, cudaFuncAttributeMaxDynamicSharedMemorySize, ATTN_SMEM);

    cudaEventRecord(ev0, 0);

    // side stream 2: Wq pair-pack
    cudaStreamWaitEvent(s2, ev0, 0);
    tohalf_pair<<<(HID_/2)*(H_*D_)/4/256, 256, 0, s2>>>(Wq, wqp, H_*D_);
    cudaEventRecord(ev2a, s2);

    // side stream 3: Wk, Wv, then Wo pair-packs
    cudaStreamWaitEvent(s3, ev0, 0);
    tohalf_pair<<<(HID_/2)*(HKV_*D_)/4/256, 256, 0, s3>>>(Wk, wkp, HKV_*D_);
    tohalf_pair<<<(HID_/2)*(HKV_*D_)/4/256, 256, 0, s3>>>(Wv, wvp, HKV_*D_);
    cudaEventRecord(ev3, s3);
    tohalf_pair<<<((H_*D_)/2)*HID_/4/256, 256, 0, s3>>>(Wo, wop, HID_);
    cudaEventRecord(ev2, s3);

    // side stream 1: gate path (exact fp32)
    cudaStreamWaitEvent(s1, ev0, 0);
    gate_proj<<<S_, 128, 0, s1>>>(hs, Wg);
    gcumsum_kernel<<<HKV_, 256, 0, s1>>>();
    cudaEventRecord(ev1, s1);

    // main stream
    tohalf_plain<<<(S_*HID_) / 1024, 256>>>(hs, hsh);
    cudaStreamWaitEvent(0, ev2a, 0);
    cudaStreamWaitEvent(0, ev3, 0);
    gemm_qkv<<<dim3(24, S_ / BM), 256, GEMM_SMEMH>>>(hsh);

    cudaStreamWaitEvent(0, ev1, 0);
    attn_kernel<<<dim3(S_ / 64, H_), 256, ATTN_SMEM>>>(cosb, sinb);

    cudaStreamWaitEvent(0, ev2, 0);
    gemm_wo<<<dim3(HID_ / BN, S_ / BM), 256, GEMM_SMEMH>>>(attnh, out);
}